// round 13
// baseline (speedup 1.0000x reference)
#include <cuda_runtime.h>
#include <cuda_bf16.h>
#include <math.h>
#include <stdint.h>

#define NN   50000
#define EE   600000
#define HH   128
#define INF  7
#define OUTF 4
#define NL   4
#define MT   128
#define NTILES ((NN + MT - 1) / MT)

// ---------------- scratch ----------------
__device__ float g_zA[NN * HH];
__device__ float g_zB[NN * HH];
__device__ __nv_bfloat16 g_aggh[NN * HH];
__device__ __nv_bfloat16 g_aggl[NN * HH];
__device__ __nv_bfloat16 g_zh[NN * HH];
__device__ __nv_bfloat16 g_zl[NN * HH];
__device__ __nv_bfloat16 g_Wth[2 * NL * HH * HH];   // [layer*2+which][n][k] (transposed)
__device__ __nv_bfloat16 g_Wtl[2 * NL * HH * HH];
__device__ int   g_deg[NN];
__device__ int   g_scan[NN];
__device__ int   g_rowptr[NN + 1];
__device__ int   g_fill[NN];
__device__ int   g_col[EE];
__device__ float g_invdeg[NN];
__device__ int   g_bsum[64];
__device__ int   g_boff[64];
__device__ float g_bnsum[HH];
__device__ float g_bnsq[HH];
__device__ float g_scale[HH];
__device__ float g_shift[HH];
__device__ int   g_is64;

__device__ __forceinline__ uint32_t smem_u32(const void* p) {
    uint32_t a;
    asm("{ .reg .u64 t; cvta.to.shared.u64 t, %1; cvt.u32.u64 %0, t; }" : "=r"(a) : "l"(p));
    return a;
}

// ---------------- warp-level tensor ops ----------------
__device__ __forceinline__ void ldsm4(uint32_t* r, uint32_t addr) {
    asm volatile("ldmatrix.sync.aligned.m8n8.x4.shared.b16 {%0,%1,%2,%3}, [%4];"
        : "=r"(r[0]), "=r"(r[1]), "=r"(r[2]), "=r"(r[3]) : "r"(addr));
}
__device__ __forceinline__ void mma16816(float* d, const uint32_t* a, const uint32_t* b) {
    asm volatile("mma.sync.aligned.m16n8k16.row.col.f32.bf16.bf16.f32 "
        "{%0,%1,%2,%3}, {%4,%5,%6,%7}, {%8,%9}, {%0,%1,%2,%3};"
        : "+f"(d[0]), "+f"(d[1]), "+f"(d[2]), "+f"(d[3])
        : "r"(a[0]), "r"(a[1]), "r"(a[2]), "r"(a[3]), "r"(b[0]), "r"(b[1]));
}

// ---------------- edge-index dtype probe ----------------
__global__ void k_detect(const int* __restrict__ ei32) {
    if (threadIdx.x == 0) {
        int z = 0;
#pragma unroll
        for (int i = 0; i < 16; i++) z |= ei32[2 * i + 1];
        g_is64 = (z == 0) ? 1 : 0;
    }
}
__device__ __forceinline__ int clampN(int v) {
    v = v < 0 ? 0 : v;
    return v >= NN ? NN - 1 : v;
}
__device__ __forceinline__ int edge_src(const void* ei, int e) {
    int v = g_is64 ? (int)((const long long*)ei)[e] : ((const int*)ei)[e];
    return clampN(v);
}
__device__ __forceinline__ int edge_dst(const void* ei, int e) {
    int v = g_is64 ? (int)((const long long*)ei)[EE + e] : ((const int*)ei)[EE + e];
    return clampN(v);
}

// ---------------- CSR build ----------------
__global__ void k_degree(const void* __restrict__ ei) {
    int e = blockIdx.x * blockDim.x + threadIdx.x;
    if (e < EE) atomicAdd(&g_deg[edge_dst(ei, e)], 1);
}
__global__ void k_scan1() {
    __shared__ int wsum[32];
    int i = blockIdx.x * 1024 + threadIdx.x;
    int v = (i < NN) ? g_deg[i] : 0;
    int lane = threadIdx.x & 31, wid = threadIdx.x >> 5;
    int x = v;
#pragma unroll
    for (int d = 1; d < 32; d <<= 1) {
        int y = __shfl_up_sync(0xFFFFFFFFu, x, d);
        if (lane >= d) x += y;
    }
    if (lane == 31) wsum[wid] = x;
    __syncthreads();
    if (wid == 0) {
        int s = wsum[lane];
#pragma unroll
        for (int d = 1; d < 32; d <<= 1) {
            int y = __shfl_up_sync(0xFFFFFFFFu, s, d);
            if (lane >= d) s += y;
        }
        wsum[lane] = s;
    }
    __syncthreads();
    int off = (wid > 0) ? wsum[wid - 1] : 0;
    int incl = x + off;
    if (i < NN) g_scan[i] = incl;
    if (threadIdx.x == 1023) g_bsum[blockIdx.x] = incl;
}
__global__ void k_scan2(int nblk) {
    int lane = threadIdx.x & 31;
    int i0 = 2 * lane, i1 = 2 * lane + 1;
    int a = (i0 < nblk) ? g_bsum[i0] : 0;
    int b = (i1 < nblk) ? g_bsum[i1] : 0;
    int s = a + b;
    int x = s;
#pragma unroll
    for (int d = 1; d < 32; d <<= 1) {
        int y = __shfl_up_sync(0xFFFFFFFFu, x, d);
        if (lane >= d) x += y;
    }
    int excl = x - s;
    if (i0 < nblk) g_boff[i0] = excl;
    if (i1 < nblk) g_boff[i1] = excl + a;
}
__global__ void k_scan3() {
    int i = blockIdx.x * blockDim.x + threadIdx.x;
    if (i < NN) {
        g_rowptr[i + 1] = g_scan[i] + g_boff[i >> 10];
        if (i == 0) g_rowptr[0] = 0;
        g_fill[i] = 0;
        int d = g_deg[i];
        g_invdeg[i] = 1.0f / (float)(d > 1 ? d : 1);
    }
}
__global__ void k_scatter(const void* __restrict__ ei) {
    int e = blockIdx.x * blockDim.x + threadIdx.x;
    if (e < EE) {
        int dst = edge_dst(ei, e);
        int src = edge_src(ei, e);
        int p = g_rowptr[dst] + atomicAdd(&g_fill[dst], 1);
        g_col[p] = src;
    }
}

// ---------------- W transpose + bf16 split ----------------
__global__ void k_wconv(const float* __restrict__ Wl, const float* __restrict__ Wr) {
    int idx = blockIdx.x * blockDim.x + threadIdx.x;
    if (idx >= 2 * NL * HH * HH) return;
    int m2 = idx / (HH * HH);
    int rem = idx - m2 * (HH * HH);
    int n = rem >> 7, k = rem & 127;
    int layer = m2 >> 1;
    const float* src = (m2 & 1) ? Wr : Wl;
    float v = src[layer * HH * HH + k * HH + n];      // B[n][k] = W[k][n]
    __nv_bfloat16 hi = __float2bfloat16_rn(v);
    __nv_bfloat16 lo = __float2bfloat16_rn(v - __bfloat162float(hi));
    g_Wth[m2 * HH * HH + n * HH + k] = hi;
    g_Wtl[m2 * HH * HH + n * HH + k] = lo;
}

// ---------------- encoder (emits fp32 z + bf16 hi/lo) ----------------
__global__ void k_enc(const float* __restrict__ x, const float* __restrict__ eW,
                      const float* __restrict__ eb, float* __restrict__ z) {
    __shared__ float W[INF * HH];
    for (int i = threadIdx.x; i < INF * HH; i += blockDim.x) W[i] = eW[i];
    __syncthreads();
    int idx = blockIdx.x * blockDim.x + threadIdx.x;
    if (idx >= NN * HH) return;
    int n = idx >> 7, h = idx & 127;
    float s = eb[h];
    const float* xr = x + n * INF;
#pragma unroll
    for (int k = 0; k < INF; k++) s = fmaf(xr[k], W[k * HH + h], s);
    z[idx] = s;
    __nv_bfloat16 hi = __float2bfloat16_rn(s);
    g_zh[idx] = hi;
    g_zl[idx] = __float2bfloat16_rn(s - __bfloat162float(hi));
}

// ---------------- split: BN finalize (per block) + BN/ReLU + bf16 split of z --
__global__ void k_split(const float* __restrict__ z,
                        const float* __restrict__ gamma, const float* __restrict__ beta) {
    int i = blockIdx.x * blockDim.x + threadIdx.x;
    if (i >= NN * (HH / 4)) return;
    int h4 = i & 31;
    float inv = 1.0f / (float)NN;
    float4 s4 = ((const float4*)g_bnsum)[h4];
    float4 q4 = ((const float4*)g_bnsq)[h4];
    float4 gm = ((const float4*)gamma)[h4];
    float4 bt = ((const float4*)beta)[h4];
    float4 sc, sh;
    { float mu = s4.x * inv; float var = q4.x * inv - mu * mu; sc.x = gm.x * rsqrtf(var + 1e-5f); sh.x = bt.x - mu * sc.x; }
    { float mu = s4.y * inv; float var = q4.y * inv - mu * mu; sc.y = gm.y * rsqrtf(var + 1e-5f); sh.y = bt.y - mu * sc.y; }
    { float mu = s4.z * inv; float var = q4.z * inv - mu * mu; sc.z = gm.z * rsqrtf(var + 1e-5f); sh.z = bt.z - mu * sc.z; }
    { float mu = s4.w * inv; float var = q4.w * inv - mu * mu; sc.w = gm.w * rsqrtf(var + 1e-5f); sh.w = bt.w - mu * sc.w; }
    if (i < 32) { ((float4*)g_scale)[i] = sc; ((float4*)g_shift)[i] = sh; }
    float4 v = ((const float4*)z)[i];
    v.x = fmaxf(fmaf(v.x, sc.x, sh.x), 0.f);
    v.y = fmaxf(fmaf(v.y, sc.y, sh.y), 0.f);
    v.z = fmaxf(fmaf(v.z, sc.z, sh.z), 0.f);
    v.w = fmaxf(fmaf(v.w, sc.w, sh.w), 0.f);
    __nv_bfloat162 hA = __floats2bfloat162_rn(v.x, v.y);
    __nv_bfloat162 hB = __floats2bfloat162_rn(v.z, v.w);
    __nv_bfloat162 lA = __floats2bfloat162_rn(v.x - __low2float(hA), v.y - __high2float(hA));
    __nv_bfloat162 lB = __floats2bfloat162_rn(v.z - __low2float(hB), v.w - __high2float(hB));
    uint2 ph, pl;
    ph.x = *(uint32_t*)&hA; ph.y = *(uint32_t*)&hB;
    pl.x = *(uint32_t*)&lA; pl.y = *(uint32_t*)&lB;
    *(uint2*)&g_zh[(size_t)i * 4] = ph;
    *(uint2*)&g_zl[(size_t)i * 4] = pl;
}

// ---------------- GEMM building blocks (R11-verified RS=80 chunk-32 path) ----
#define RS      80
#define CH_TILE (128 * RS)
#define OFF_AH  0
#define OFF_AL  (2 * CH_TILE)
#define OFF_BH  (4 * CH_TILE)
#define OFF_BL  (6 * CH_TILE)
#define GEMM_SMEM (8 * CH_TILE)

__device__ __forceinline__ void cpa16(uint32_t dst, const void* src, uint32_t zf) {
    asm volatile("cp.async.cg.shared.global [%0], [%1], 16, %2;"
        :: "r"(dst), "l"(src), "r"(zf) : "memory");
}
__device__ __forceinline__ void cpa16u(uint32_t dst, const void* src) {
    asm volatile("cp.async.cg.shared.global [%0], [%1], 16;"
        :: "r"(dst), "l"(src) : "memory");
}
__device__ __forceinline__ void stage_chunk(uint32_t sb, int b,
        const __nv_bfloat16* ah, const __nv_bfloat16* al,
        const __nv_bfloat16* bh, const __nv_bfloat16* bl,
        int colofs, int row0, int t) {
    int row = t >> 2, ch = t & 3;
    uint32_t sw = (uint32_t)(row * RS + ch * 16) + b * CH_TILE;
    int gr = row0 + row;
    uint32_t zf = (gr < NN) ? 16u : 0u;
    size_t ao = (size_t)gr * HH + colofs + ch * 8;
    cpa16(sb + OFF_AH + sw, ah + ao, zf);
    cpa16(sb + OFF_AL + sw, al + ao, zf);
    size_t bo = (size_t)row * HH + colofs + ch * 8;
    cpa16u(sb + OFF_BH + sw, bh + bo);
    cpa16u(sb + OFF_BL + sw, bl + bo);
    asm volatile("cp.async.commit_group;" ::: "memory");
}
__device__ __forceinline__ void compute_chunk(uint32_t sb, int b, int m0, int n0,
        int a_row, int a_chd, int b_row, int b_chd, float d[2][4][4]) {
    uint32_t aH = sb + OFF_AH + b * CH_TILE;
    uint32_t aL = sb + OFF_AL + b * CH_TILE;
    uint32_t bH = sb + OFF_BH + b * CH_TILE;
    uint32_t bL = sb + OFF_BL + b * CH_TILE;
#pragma unroll
    for (int ks = 0; ks < 2; ks++) {
        int c = ks * 2;
        uint32_t ah[2][4], al[2][4], bh[2][4], bl[2][4];
#pragma unroll
        for (int mt = 0; mt < 2; mt++) {
            int row = m0 + mt * 16 + a_row;
            uint32_t o = (uint32_t)(row * RS + (c + a_chd) * 16);
            ldsm4(ah[mt], aH + o);
            ldsm4(al[mt], aL + o);
        }
#pragma unroll
        for (int np = 0; np < 2; np++) {
            int row = n0 + np * 16 + b_row;
            uint32_t o = (uint32_t)(row * RS + (c + b_chd) * 16);
            ldsm4(bh[np], bH + o);
            ldsm4(bl[np], bL + o);
        }
#pragma unroll
        for (int mt = 0; mt < 2; mt++)
#pragma unroll
            for (int nt = 0; nt < 4; nt++) {
                const uint32_t* fh = &bh[nt >> 1][(nt & 1) * 2];
                const uint32_t* fl = &bl[nt >> 1][(nt & 1) * 2];
                mma16816(d[mt][nt], ah[mt], fh);
                mma16816(d[mt][nt], ah[mt], fl);
                mma16816(d[mt][nt], al[mt], fh);
            }
    }
}
// runs the K=128 GEMM of one operand pair into d (4 chunks of 32, double buffer)
__device__ __forceinline__ void gemm_k128(uint32_t sb, int row0, int t,
        const __nv_bfloat16* Ah, const __nv_bfloat16* Al,
        const __nv_bfloat16* Bh, const __nv_bfloat16* Bl,
        int m0, int n0, int a_row, int a_chd, int b_row, int b_chd, float d[2][4][4]) {
    stage_chunk(sb, 0, Ah, Al, Bh, Bl, 0, row0, t);
#pragma unroll
    for (int c = 0; c < 4; c++) {
        if (c + 1 < 4) {
            stage_chunk(sb, (c + 1) & 1, Ah, Al, Bh, Bl, (c + 1) * 32, row0, t);
            asm volatile("cp.async.wait_group 1;" ::: "memory");
        } else {
            asm volatile("cp.async.wait_group 0;" ::: "memory");
        }
        __syncthreads();
        compute_chunk(sb, c & 1, m0, n0, a_row, a_chd, b_row, b_chd, d);
        __syncthreads();
    }
}

// ---------------- fused: gather (8/9 of blocks) || z@Wr partial GEMM (1/9) ----
__global__ void __launch_bounds__(512, 1)
k_fused(const float* __restrict__ zin, int apply_bn,
        const __nv_bfloat16* __restrict__ wrh, const __nv_bfloat16* __restrict__ wrl,
        float* __restrict__ zout) {
    extern __shared__ char smb[];
    const int bid = blockIdx.x;
    const int t = threadIdx.x, wid = t >> 5, lane = t & 31;

    if (bid % 9 != 0) {
        // ---- gather role: warp per node ----
        if (bid == 1 && t < HH) { g_bnsum[t] = 0.f; g_bnsq[t] = 0.f; }
        int gb = bid - 1 - bid / 9;             // dense index among gather blocks
        int w = gb * 16 + wid;
        if (w >= NN) return;
        float4 sc = make_float4(1.f, 1.f, 1.f, 1.f);
        float4 sh = make_float4(0.f, 0.f, 0.f, 0.f);
        if (apply_bn) {
            sc = ((const float4*)g_scale)[lane];
            sh = ((const float4*)g_shift)[lane];
        }
        int beg = g_rowptr[w], end = g_rowptr[w + 1];
        float4 acc = make_float4(0.f, 0.f, 0.f, 0.f);
        for (int j = beg; j < end; j++) {
            int s = g_col[j];
            float4 v = *(const float4*)&zin[(size_t)s * HH + lane * 4];
            if (apply_bn) {
                v.x = fmaxf(fmaf(v.x, sc.x, sh.x), 0.f);
                v.y = fmaxf(fmaf(v.y, sc.y, sh.y), 0.f);
                v.z = fmaxf(fmaf(v.z, sc.z, sh.z), 0.f);
                v.w = fmaxf(fmaf(v.w, sc.w, sh.w), 0.f);
            }
            acc.x += v.x; acc.y += v.y; acc.z += v.z; acc.w += v.w;
        }
        float id = g_invdeg[w];
        acc.x *= id; acc.y *= id; acc.z *= id; acc.w *= id;
        __nv_bfloat162 hA = __floats2bfloat162_rn(acc.x, acc.y);
        __nv_bfloat162 hB = __floats2bfloat162_rn(acc.z, acc.w);
        __nv_bfloat162 lA = __floats2bfloat162_rn(acc.x - __low2float(hA), acc.y - __high2float(hA));
        __nv_bfloat162 lB = __floats2bfloat162_rn(acc.z - __low2float(hB), acc.w - __high2float(hB));
        uint2 ph, pl;
        ph.x = *(uint32_t*)&hA; ph.y = *(uint32_t*)&hB;
        pl.x = *(uint32_t*)&lA; pl.y = *(uint32_t*)&lB;
        *(uint2*)&g_aggh[(size_t)w * HH + lane * 4] = ph;
        *(uint2*)&g_aggl[(size_t)w * HH + lane * 4] = pl;
        return;
    }

    // ---- gemm_z role: zout_partial = z @ Wr ----
    uint32_t sb = smem_u32(smb);
    const int tile = bid / 9;
    const int m0 = (wid & 3) * 32, n0 = (wid >> 2) * 32;
    const int row0 = tile * MT;
    const int g = lane >> 2, tid4 = lane & 3;
    const int a_row = lane & 15, a_chd = lane >> 4;
    const int b_row = (lane & 7) + ((lane >> 4) << 3), b_chd = (lane >> 3) & 1;

    float d[2][4][4];
#pragma unroll
    for (int mt = 0; mt < 2; mt++)
#pragma unroll
        for (int nt = 0; nt < 4; nt++)
#pragma unroll
            for (int j = 0; j < 4; j++) d[mt][nt][j] = 0.f;

    gemm_k128(sb, row0, t, g_zh, g_zl, wrh, wrl, m0, n0, a_row, a_chd, b_row, b_chd, d);

#pragma unroll
    for (int mt = 0; mt < 2; mt++) {
        int r_up = row0 + m0 + mt * 16 + g;
        int r_dn = r_up + 8;
#pragma unroll
        for (int nt = 0; nt < 4; nt++) {
            int cc = n0 + nt * 8 + tid4 * 2;
            if (r_up < NN)
                *(float2*)&zout[(size_t)r_up * HH + cc] = make_float2(d[mt][nt][0], d[mt][nt][1]);
            if (r_dn < NN)
                *(float2*)&zout[(size_t)r_dn * HH + cc] = make_float2(d[mt][nt][2], d[mt][nt][3]);
        }
    }
}

// ---------------- agg @ Wl, accumulate onto partial, + bias + BN stats --------
__global__ void __launch_bounds__(512, 1)
k_gemm_agg(const __nv_bfloat16* __restrict__ wlh, const __nv_bfloat16* __restrict__ wll,
           const float* __restrict__ bias, float* __restrict__ zout, int do_stats) {
    extern __shared__ char smb[];
    uint32_t sb = smem_u32(smb);
    const int t = threadIdx.x, wid = t >> 5, lane = t & 31;
    const int m0 = (wid & 3) * 32, n0 = (wid >> 2) * 32;
    const int row0 = blockIdx.x * MT;
    const int g = lane >> 2, tid4 = lane & 3;
    const int a_row = lane & 15, a_chd = lane >> 4;
    const int b_row = (lane & 7) + ((lane >> 4) << 3), b_chd = (lane >> 3) & 1;

    float d[2][4][4];
#pragma unroll
    for (int mt = 0; mt < 2; mt++)
#pragma unroll
        for (int nt = 0; nt < 4; nt++)
#pragma unroll
            for (int j = 0; j < 4; j++) d[mt][nt][j] = 0.f;

    gemm_k128(sb, row0, t, g_aggh, g_aggl, wlh, wll, m0, n0, a_row, a_chd, b_row, b_chd, d);

    float* ssum = (float*)smb;
    float* ssq  = ssum + HH;
    if (do_stats && t < 2 * HH) ssum[t] = 0.f;
    __syncthreads();

    float s_acc[4][2], q_acc[4][2];
#pragma unroll
    for (int nt = 0; nt < 4; nt++) { s_acc[nt][0] = s_acc[nt][1] = 0.f; q_acc[nt][0] = q_acc[nt][1] = 0.f; }

#pragma unroll
    for (int mt = 0; mt < 2; mt++) {
        int r_up = row0 + m0 + mt * 16 + g;
        int r_dn = r_up + 8;
#pragma unroll
        for (int nt = 0; nt < 4; nt++) {
            int cc = n0 + nt * 8 + tid4 * 2;
            float b0 = bias[cc], b1 = bias[cc + 1];
            if (r_up < NN) {
                float2 p = *(float2*)&zout[(size_t)r_up * HH + cc];
                float v0 = d[mt][nt][0] + p.x + b0, v1 = d[mt][nt][1] + p.y + b1;
                *(float2*)&zout[(size_t)r_up * HH + cc] = make_float2(v0, v1);
                s_acc[nt][0] += v0; q_acc[nt][0] = fmaf(v0, v0, q_acc[nt][0]);
                s_acc[nt][1] += v1; q_acc[nt][1] = fmaf(v1, v1, q_acc[nt][1]);
            }
            if (r_dn < NN) {
                float2 p = *(float2*)&zout[(size_t)r_dn * HH + cc];
                float v2 = d[mt][nt][2] + p.x + b0, v3 = d[mt][nt][3] + p.y + b1;
                *(float2*)&zout[(size_t)r_dn * HH + cc] = make_float2(v2, v3);
                s_acc[nt][0] += v2; q_acc[nt][0] = fmaf(v2, v2, q_acc[nt][0]);
                s_acc[nt][1] += v3; q_acc[nt][1] = fmaf(v3, v3, q_acc[nt][1]);
            }
        }
    }

    if (do_stats) {
#pragma unroll
        for (int nt = 0; nt < 4; nt++)
#pragma unroll
            for (int j = 0; j < 2; j++) {
                float sv = s_acc[nt][j], qv = q_acc[nt][j];
                sv += __shfl_down_sync(0xFFFFFFFFu, sv, 16);
                qv += __shfl_down_sync(0xFFFFFFFFu, qv, 16);
                sv += __shfl_down_sync(0xFFFFFFFFu, sv, 8);
                qv += __shfl_down_sync(0xFFFFFFFFu, qv, 8);
                sv += __shfl_down_sync(0xFFFFFFFFu, sv, 4);
                qv += __shfl_down_sync(0xFFFFFFFFu, qv, 4);
                if (g == 0) {
                    int cc = n0 + nt * 8 + tid4 * 2 + j;
                    atomicAdd(&ssum[cc], sv);
                    atomicAdd(&ssq[cc], qv);
                }
            }
        __syncthreads();
        if (t < HH) {
            atomicAdd(&g_bnsum[t], ssum[t]);
            atomicAdd(&g_bnsq[t], ssq[t]);
        }
    }
}

// ---------------- decoder ----------------
__global__ void k_dec(const float* __restrict__ z, const float* __restrict__ dW,
                      const float* __restrict__ db, float* __restrict__ out) {
    __shared__ float W[HH * OUTF];
    for (int i = threadIdx.x; i < HH * OUTF; i += blockDim.x) W[i] = dW[i];
    __syncthreads();
    int w = (blockIdx.x * blockDim.x + threadIdx.x) >> 5;
    int lane = threadIdx.x & 31;
    if (w >= NN) return;
    float4 zv = *(const float4*)&z[(size_t)w * HH + lane * 4];
    int h = lane * 4;
    float o0 = zv.x * W[h * 4 + 0] + zv.y * W[(h + 1) * 4 + 0] + zv.z * W[(h + 2) * 4 + 0] + zv.w * W[(h + 3) * 4 + 0];
    float o1 = zv.x * W[h * 4 + 1] + zv.y * W[(h + 1) * 4 + 1] + zv.z * W[(h + 2) * 4 + 1] + zv.w * W[(h + 3) * 4 + 1];
    float o2 = zv.x * W[h * 4 + 2] + zv.y * W[(h + 1) * 4 + 2] + zv.z * W[(h + 2) * 4 + 2] + zv.w * W[(h + 3) * 4 + 2];
    float o3 = zv.x * W[h * 4 + 3] + zv.y * W[(h + 1) * 4 + 3] + zv.z * W[(h + 2) * 4 + 3] + zv.w * W[(h + 3) * 4 + 3];
#pragma unroll
    for (int d = 16; d; d >>= 1) {
        o0 += __shfl_down_sync(0xFFFFFFFFu, o0, d);
        o1 += __shfl_down_sync(0xFFFFFFFFu, o1, d);
        o2 += __shfl_down_sync(0xFFFFFFFFu, o2, d);
        o3 += __shfl_down_sync(0xFFFFFFFFu, o3, d);
    }
    if (lane == 0) {
        float4 r;
        r.x = o0 + db[0]; r.y = o1 + db[1]; r.z = o2 + db[2]; r.w = o3 + db[3];
        *(float4*)&out[w * 4] = r;
    }
}

// ---------------- launch ----------------
extern "C" void kernel_launch(void* const* d_in, const int* in_sizes, int n_in,
                              void* d_out, int out_size) {
    const float* x      = (const float*)d_in[0];
    const float* enc_W  = (const float*)d_in[1];
    const float* enc_b  = (const float*)d_in[2];
    const float* Wl     = (const float*)d_in[3];
    const float* Wr     = (const float*)d_in[4];
    const float* b      = (const float*)d_in[5];
    const float* bng    = (const float*)d_in[6];
    const float* bnb    = (const float*)d_in[7];
    const float* dec_W  = (const float*)d_in[8];
    const float* dec_b  = (const float*)d_in[9];
    const void*  ei     = d_in[10];
    float* out = (float*)d_out;

    float *zA, *zB;
    __nv_bfloat16 *Wth, *Wtl;
    void* p;
    cudaGetSymbolAddress(&p, g_zA);  zA  = (float*)p;
    cudaGetSymbolAddress(&p, g_zB);  zB  = (float*)p;
    cudaGetSymbolAddress(&p, g_Wth); Wth = (__nv_bfloat16*)p;
    cudaGetSymbolAddress(&p, g_Wtl); Wtl = (__nv_bfloat16*)p;
    void* pdeg;
    cudaGetSymbolAddress(&pdeg, g_deg);

    cudaFuncSetAttribute(k_fused, cudaFuncAttributeMaxDynamicSharedMemorySize, GEMM_SMEM);
    cudaFuncSetAttribute(k_gemm_agg, cudaFuncAttributeMaxDynamicSharedMemorySize, GEMM_SMEM);

    const int TB = 256;
    const int egrid = (EE + TB - 1) / TB;

    // CSR build + W conversion
    k_detect<<<1, 32>>>((const int*)ei);
    cudaMemsetAsync(pdeg, 0, NN * sizeof(int));
    k_degree<<<egrid, TB>>>(ei);
    k_scan1<<<(NN + 1023) / 1024, 1024>>>();
    k_scan2<<<1, 32>>>((NN + 1023) / 1024);
    k_scan3<<<(NN + TB - 1) / TB, TB>>>();
    k_scatter<<<egrid, TB>>>(ei);
    k_wconv<<<(2 * NL * HH * HH + TB - 1) / TB, TB>>>(Wl, Wr);

    k_enc<<<(NN * HH + TB - 1) / TB, TB>>>(x, enc_W, enc_b, zA);

    float* zin = zA;
    float* zout = zB;
    for (int i = 0; i < NL; i++) {
        if (i > 0)
            k_split<<<(NN * (HH / 4) + TB - 1) / TB, TB>>>(zin, bng + (size_t)(i - 1) * HH,
                                                           bnb + (size_t)(i - 1) * HH);
        k_fused<<<9 * NTILES, 512, GEMM_SMEM>>>(zin, i > 0,
                Wth + (size_t)(2 * i + 1) * HH * HH, Wtl + (size_t)(2 * i + 1) * HH * HH, zout);
        k_gemm_agg<<<NTILES, 512, GEMM_SMEM>>>(
                Wth + (size_t)(2 * i + 0) * HH * HH, Wtl + (size_t)(2 * i + 0) * HH * HH,
                b + (size_t)i * HH, zout, i < NL - 1);
        float* tmp = zin; zin = zout; zout = tmp;
    }

    k_dec<<<(NN * 32 + TB - 1) / TB, TB>>>(zin, dec_W, dec_b, out);
}

// round 14
// speedup vs baseline: 1.5791x; 1.5791x over previous
#include <cuda_runtime.h>
#include <cuda_bf16.h>
#include <math.h>
#include <stdint.h>

#define NN   50000
#define EE   600000
#define HH   128
#define INF  7
#define OUTF 4
#define NL   4
#define MT   128
#define NTILES ((NN + MT - 1) / MT)

// ---------------- scratch ----------------
__device__ float g_zA[NN * HH];
__device__ float g_zB[NN * HH];
__device__ __nv_bfloat16 g_aggh[NN * HH];
__device__ __nv_bfloat16 g_aggl[NN * HH];
__device__ __nv_bfloat16 g_zh[NN * HH];
__device__ __nv_bfloat16 g_zl[NN * HH];
__device__ __nv_bfloat16 g_Wth[2 * NL * HH * HH];   // [layer*2+which][n][k] (transposed)
__device__ __nv_bfloat16 g_Wtl[2 * NL * HH * HH];
__device__ int   g_deg[NN];
__device__ int   g_scan[NN];
__device__ int   g_rowptr[NN + 1];
__device__ int   g_fill[NN];
__device__ int   g_col[EE];
__device__ float g_invdeg[NN];
__device__ int   g_bsum[64];
__device__ int   g_boff[64];
__device__ float g_bnsum[(NL - 1) * HH];   // per-layer stat buffers (no inter-kernel race)
__device__ float g_bnsq[(NL - 1) * HH];
__device__ int   g_is64;

__device__ __forceinline__ uint32_t smem_u32(const void* p) {
    uint32_t a;
    asm("{ .reg .u64 t; cvta.to.shared.u64 t, %1; cvt.u32.u64 %0, t; }" : "=r"(a) : "l"(p));
    return a;
}

// ---------------- warp-level tensor ops (baseline PTX, sm_80+) ----------------
__device__ __forceinline__ void ldsm4(uint32_t* r, uint32_t addr) {
    asm volatile("ldmatrix.sync.aligned.m8n8.x4.shared.b16 {%0,%1,%2,%3}, [%4];"
        : "=r"(r[0]), "=r"(r[1]), "=r"(r[2]), "=r"(r[3]) : "r"(addr));
}
__device__ __forceinline__ void mma16816(float* d, const uint32_t* a, const uint32_t* b) {
    asm volatile("mma.sync.aligned.m16n8k16.row.col.f32.bf16.bf16.f32 "
        "{%0,%1,%2,%3}, {%4,%5,%6,%7}, {%8,%9}, {%0,%1,%2,%3};"
        : "+f"(d[0]), "+f"(d[1]), "+f"(d[2]), "+f"(d[3])
        : "r"(a[0]), "r"(a[1]), "r"(a[2]), "r"(a[3]), "r"(b[0]), "r"(b[1]));
}

// ---------------- edge-index dtype probe ----------------
__global__ void k_detect(const int* __restrict__ ei32) {
    if (threadIdx.x == 0) {
        int z = 0;
#pragma unroll
        for (int i = 0; i < 16; i++) z |= ei32[2 * i + 1];
        g_is64 = (z == 0) ? 1 : 0;
    }
}
__device__ __forceinline__ int clampN(int v) {
    v = v < 0 ? 0 : v;
    return v >= NN ? NN - 1 : v;
}
__device__ __forceinline__ int edge_src(const void* ei, int e) {
    int v = g_is64 ? (int)((const long long*)ei)[e] : ((const int*)ei)[e];
    return clampN(v);
}
__device__ __forceinline__ int edge_dst(const void* ei, int e) {
    int v = g_is64 ? (int)((const long long*)ei)[EE + e] : ((const int*)ei)[EE + e];
    return clampN(v);
}

// ---------------- CSR build ----------------
__global__ void k_degree(const void* __restrict__ ei) {
    int e = blockIdx.x * blockDim.x + threadIdx.x;
    if (e < EE) atomicAdd(&g_deg[edge_dst(ei, e)], 1);
}
__global__ void k_scan1() {
    __shared__ int wsum[32];
    int i = blockIdx.x * 1024 + threadIdx.x;
    int v = (i < NN) ? g_deg[i] : 0;
    int lane = threadIdx.x & 31, wid = threadIdx.x >> 5;
    int x = v;
#pragma unroll
    for (int d = 1; d < 32; d <<= 1) {
        int y = __shfl_up_sync(0xFFFFFFFFu, x, d);
        if (lane >= d) x += y;
    }
    if (lane == 31) wsum[wid] = x;
    __syncthreads();
    if (wid == 0) {
        int s = wsum[lane];
#pragma unroll
        for (int d = 1; d < 32; d <<= 1) {
            int y = __shfl_up_sync(0xFFFFFFFFu, s, d);
            if (lane >= d) s += y;
        }
        wsum[lane] = s;
    }
    __syncthreads();
    int off = (wid > 0) ? wsum[wid - 1] : 0;
    int incl = x + off;
    if (i < NN) g_scan[i] = incl;
    if (threadIdx.x == 1023) g_bsum[blockIdx.x] = incl;
}
__global__ void k_scan2(int nblk) {
    int lane = threadIdx.x & 31;
    int i0 = 2 * lane, i1 = 2 * lane + 1;
    int a = (i0 < nblk) ? g_bsum[i0] : 0;
    int b = (i1 < nblk) ? g_bsum[i1] : 0;
    int s = a + b;
    int x = s;
#pragma unroll
    for (int d = 1; d < 32; d <<= 1) {
        int y = __shfl_up_sync(0xFFFFFFFFu, x, d);
        if (lane >= d) x += y;
    }
    int excl = x - s;
    if (i0 < nblk) g_boff[i0] = excl;
    if (i1 < nblk) g_boff[i1] = excl + a;
}
__global__ void k_scan3() {
    int i = blockIdx.x * blockDim.x + threadIdx.x;
    if (i < NN) {
        g_rowptr[i + 1] = g_scan[i] + g_boff[i >> 10];
        if (i == 0) g_rowptr[0] = 0;
        g_fill[i] = 0;
        int d = g_deg[i];
        g_invdeg[i] = 1.0f / (float)(d > 1 ? d : 1);
    }
}
__global__ void k_scatter(const void* __restrict__ ei) {
    int e = blockIdx.x * blockDim.x + threadIdx.x;
    if (e < EE) {
        int dst = edge_dst(ei, e);
        int src = edge_src(ei, e);
        int p = g_rowptr[dst] + atomicAdd(&g_fill[dst], 1);
        g_col[p] = src;
    }
}

// ---------------- W transpose + bf16 split (once per launch) ----------------
__global__ void k_wconv(const float* __restrict__ Wl, const float* __restrict__ Wr) {
    int idx = blockIdx.x * blockDim.x + threadIdx.x;
    if (idx >= 2 * NL * HH * HH) return;
    int m2 = idx / (HH * HH);
    int rem = idx - m2 * (HH * HH);
    int n = rem >> 7, k = rem & 127;
    int layer = m2 >> 1;
    const float* src = (m2 & 1) ? Wr : Wl;
    float v = src[layer * HH * HH + k * HH + n];      // B[n][k] = W[k][n]
    __nv_bfloat16 hi = __float2bfloat16_rn(v);
    __nv_bfloat16 lo = __float2bfloat16_rn(v - __bfloat162float(hi));
    g_Wth[m2 * HH * HH + n * HH + k] = hi;
    g_Wtl[m2 * HH * HH + n * HH + k] = lo;
}

// ---------------- encoder (fp32 z; zeroes per-layer BN stat buffers) ---------
__global__ void k_enc(const float* __restrict__ x, const float* __restrict__ eW,
                      const float* __restrict__ eb, float* __restrict__ z) {
    __shared__ float W[INF * HH];
    int gid = blockIdx.x * blockDim.x + threadIdx.x;
    if (gid < (NL - 1) * HH) { g_bnsum[gid] = 0.f; g_bnsq[gid] = 0.f; }
    for (int i = threadIdx.x; i < INF * HH; i += blockDim.x) W[i] = eW[i];
    __syncthreads();
    if (gid >= NN * HH) return;
    int n = gid >> 7, h = gid & 127;
    float s = eb[h];
    const float* xr = x + n * INF;
#pragma unroll
    for (int k = 0; k < INF; k++) s = fmaf(xr[k], W[k * HH + h], s);
    z[gid] = s;
}

// ---------------- aggregation: inline BN finalize + fused BN/ReLU gather +
//                  own-row bf16 split (layer==0: no BN) -----------------------
__global__ void k_agg(const float* __restrict__ zin, int layer,
                      const float* __restrict__ gamma, const float* __restrict__ beta) {
    int w = (blockIdx.x * blockDim.x + threadIdx.x) >> 5;
    int lane = threadIdx.x & 31;
    if (w >= NN) return;
    float4 sc = make_float4(1.f, 1.f, 1.f, 1.f);
    float4 sh = make_float4(0.f, 0.f, 0.f, 0.f);
    if (layer > 0) {
        // inline BN finalize from previous layer's sums (identical math to old k_bnfin)
        const float inv = 1.0f / (float)NN;
        float4 s4 = ((const float4*)(g_bnsum + (size_t)(layer - 1) * HH))[lane];
        float4 q4 = ((const float4*)(g_bnsq + (size_t)(layer - 1) * HH))[lane];
        float4 gm = ((const float4*)gamma)[lane];
        float4 bt = ((const float4*)beta)[lane];
        { float mu = s4.x * inv; float var = q4.x * inv - mu * mu; sc.x = gm.x * rsqrtf(var + 1e-5f); sh.x = bt.x - mu * sc.x; }
        { float mu = s4.y * inv; float var = q4.y * inv - mu * mu; sc.y = gm.y * rsqrtf(var + 1e-5f); sh.y = bt.y - mu * sc.y; }
        { float mu = s4.z * inv; float var = q4.z * inv - mu * mu; sc.z = gm.z * rsqrtf(var + 1e-5f); sh.z = bt.z - mu * sc.z; }
        { float mu = s4.w * inv; float var = q4.w * inv - mu * mu; sc.w = gm.w * rsqrtf(var + 1e-5f); sh.w = bt.w - mu * sc.w; }
    }

    // own-row: BN+ReLU (if any) then bf16 hi/lo split for the GEMM z operand
    {
        float4 v = *(const float4*)&zin[(size_t)w * HH + lane * 4];
        if (layer > 0) {
            v.x = fmaxf(fmaf(v.x, sc.x, sh.x), 0.f);
            v.y = fmaxf(fmaf(v.y, sc.y, sh.y), 0.f);
            v.z = fmaxf(fmaf(v.z, sc.z, sh.z), 0.f);
            v.w = fmaxf(fmaf(v.w, sc.w, sh.w), 0.f);
        }
        __nv_bfloat162 hA = __floats2bfloat162_rn(v.x, v.y);
        __nv_bfloat162 hB = __floats2bfloat162_rn(v.z, v.w);
        __nv_bfloat162 lA = __floats2bfloat162_rn(v.x - __low2float(hA), v.y - __high2float(hA));
        __nv_bfloat162 lB = __floats2bfloat162_rn(v.z - __low2float(hB), v.w - __high2float(hB));
        uint2 ph, pl;
        ph.x = *(uint32_t*)&hA; ph.y = *(uint32_t*)&hB;
        pl.x = *(uint32_t*)&lA; pl.y = *(uint32_t*)&lB;
        *(uint2*)&g_zh[(size_t)w * HH + lane * 4] = ph;
        *(uint2*)&g_zl[(size_t)w * HH + lane * 4] = pl;
    }

    int beg = g_rowptr[w], end = g_rowptr[w + 1];
    float4 acc = make_float4(0.f, 0.f, 0.f, 0.f);
    for (int j = beg; j < end; j++) {
        int s = g_col[j];
        float4 v = *(const float4*)&zin[(size_t)s * HH + lane * 4];
        if (layer > 0) {
            v.x = fmaxf(fmaf(v.x, sc.x, sh.x), 0.f);
            v.y = fmaxf(fmaf(v.y, sc.y, sh.y), 0.f);
            v.z = fmaxf(fmaf(v.z, sc.z, sh.z), 0.f);
            v.w = fmaxf(fmaf(v.w, sc.w, sh.w), 0.f);
        }
        acc.x += v.x; acc.y += v.y; acc.z += v.z; acc.w += v.w;
    }
    float id = g_invdeg[w];
    acc.x *= id; acc.y *= id; acc.z *= id; acc.w *= id;
    __nv_bfloat162 hA = __floats2bfloat162_rn(acc.x, acc.y);
    __nv_bfloat162 hB = __floats2bfloat162_rn(acc.z, acc.w);
    __nv_bfloat162 lA = __floats2bfloat162_rn(acc.x - __low2float(hA), acc.y - __high2float(hA));
    __nv_bfloat162 lB = __floats2bfloat162_rn(acc.z - __low2float(hB), acc.w - __high2float(hB));
    uint2 ph, pl;
    ph.x = *(uint32_t*)&hA; ph.y = *(uint32_t*)&hB;
    pl.x = *(uint32_t*)&lA; pl.y = *(uint32_t*)&lB;
    *(uint2*)&g_aggh[(size_t)w * HH + lane * 4] = ph;
    *(uint2*)&g_aggl[(size_t)w * HH + lane * 4] = pl;
}

// ---------------- HMMA GEMM: zout = [agg|z] @ [Wl;Wr] + b  (K=256 pipelined) --
// R10/R12 config: 512 threads, warp tile 32x32, 4 K-chunks of 64,
// cp.async double buffering, XOR swizzle, 1 CTA/SM. Fused BN stats epilogue
// (atomics into the per-layer stat buffer).
#define CH_TILE 16384
#define OFF_AH  0
#define OFF_AL  32768
#define OFF_BH  65536
#define OFF_BL  98304
#define GEMM_SMEM 131072

__device__ __forceinline__ void cpa16(uint32_t dst, const void* src, uint32_t zf) {
    asm volatile("cp.async.cg.shared.global [%0], [%1], 16, %2;"
        :: "r"(dst), "l"(src), "r"(zf) : "memory");
}
__device__ __forceinline__ void cpa16u(uint32_t dst, const void* src) {
    asm volatile("cp.async.cg.shared.global [%0], [%1], 16;"
        :: "r"(dst), "l"(src) : "memory");
}

__device__ __forceinline__ void stage_chunk(uint32_t sb, int b,
        const __nv_bfloat16* ah, const __nv_bfloat16* al,
        const __nv_bfloat16* bh, const __nv_bfloat16* bl,
        int colofs, int row0, int t) {
    for (int i = t; i < 1024; i += 512) {
        int row = i >> 3, ch = i & 7;
        uint32_t sw = (uint32_t)(row * 128 + ((ch ^ (row & 7)) * 16));
        int gr = row0 + row;
        uint32_t zf = (gr < NN) ? 16u : 0u;
        size_t ao = (size_t)gr * HH + colofs + ch * 8;
        cpa16(sb + OFF_AH + b * CH_TILE + sw, ah + ao, zf);
        cpa16(sb + OFF_AL + b * CH_TILE + sw, al + ao, zf);
        size_t bo = (size_t)row * HH + colofs + ch * 8;
        cpa16u(sb + OFF_BH + b * CH_TILE + sw, bh + bo);
        cpa16u(sb + OFF_BL + b * CH_TILE + sw, bl + bo);
    }
    asm volatile("cp.async.commit_group;" ::: "memory");
}

__device__ __forceinline__ void compute_chunk(uint32_t sb, int b, int m0, int n0,
        int a_row, int a_chd, int b_row, int b_chd, float d[2][4][4]) {
    uint32_t aH = sb + OFF_AH + b * CH_TILE;
    uint32_t aL = sb + OFF_AL + b * CH_TILE;
    uint32_t bH = sb + OFF_BH + b * CH_TILE;
    uint32_t bL = sb + OFF_BL + b * CH_TILE;
#pragma unroll
    for (int ks = 0; ks < 4; ks++) {
        int c = ks * 2;
        uint32_t ah[2][4], al[2][4], bh[2][4], bl[2][4];
#pragma unroll
        for (int mt = 0; mt < 2; mt++) {
            int row = m0 + mt * 16 + a_row;
            int ch = c + a_chd;
            uint32_t o = (uint32_t)(row * 128 + ((ch ^ (row & 7)) * 16));
            ldsm4(ah[mt], aH + o);
            ldsm4(al[mt], aL + o);
        }
#pragma unroll
        for (int np = 0; np < 2; np++) {
            int row = n0 + np * 16 + b_row;
            int ch = c + b_chd;
            uint32_t o = (uint32_t)(row * 128 + ((ch ^ (row & 7)) * 16));
            ldsm4(bh[np], bH + o);
            ldsm4(bl[np], bL + o);
        }
#pragma unroll
        for (int mt = 0; mt < 2; mt++)
#pragma unroll
            for (int nt = 0; nt < 4; nt++) {
                const uint32_t* fh = &bh[nt >> 1][(nt & 1) * 2];
                const uint32_t* fl = &bl[nt >> 1][(nt & 1) * 2];
                mma16816(d[mt][nt], ah[mt], fh);   // hi*hi
                mma16816(d[mt][nt], ah[mt], fl);   // hi*lo
                mma16816(d[mt][nt], al[mt], fh);   // lo*hi
            }
    }
}

__global__ void __launch_bounds__(512, 1)
k_gemm_mma(const __nv_bfloat16* __restrict__ wlh, const __nv_bfloat16* __restrict__ wll,
           const __nv_bfloat16* __restrict__ wrh, const __nv_bfloat16* __restrict__ wrl,
           const float* __restrict__ bias, float* __restrict__ zout, int stats_layer) {
    extern __shared__ char smb[];
    uint32_t sb = smem_u32(smb);
    const int t = threadIdx.x, wid = t >> 5, lane = t & 31;
    const int m0 = (wid & 3) * 32;
    const int n0 = (wid >> 2) * 32;
    const int row0 = blockIdx.x * MT;
    const int g = lane >> 2, tid4 = lane & 3;
    const int do_stats = (stats_layer >= 0);

    const int a_row = lane & 15, a_chd = lane >> 4;
    const int b_row = (lane & 7) + ((lane >> 4) << 3), b_chd = (lane >> 3) & 1;

    float d[2][4][4];
#pragma unroll
    for (int mt = 0; mt < 2; mt++)
#pragma unroll
        for (int nt = 0; nt < 4; nt++)
#pragma unroll
            for (int j = 0; j < 4; j++) d[mt][nt][j] = 0.f;

    const __nv_bfloat16* Ah[4] = {g_aggh, g_aggh, g_zh, g_zh};
    const __nv_bfloat16* Al[4] = {g_aggl, g_aggl, g_zl, g_zl};
    const __nv_bfloat16* Bh[4] = {wlh, wlh, wrh, wrh};
    const __nv_bfloat16* Bl[4] = {wll, wll, wrl, wrl};

    stage_chunk(sb, 0, Ah[0], Al[0], Bh[0], Bl[0], 0, row0, t);
#pragma unroll
    for (int c = 0; c < 4; c++) {
        if (c + 1 < 4) {
            stage_chunk(sb, (c + 1) & 1, Ah[c + 1], Al[c + 1], Bh[c + 1], Bl[c + 1],
                        ((c + 1) & 1) * 64, row0, t);
            asm volatile("cp.async.wait_group 1;" ::: "memory");
        } else {
            asm volatile("cp.async.wait_group 0;" ::: "memory");
        }
        __syncthreads();
        compute_chunk(sb, c & 1, m0, n0, a_row, a_chd, b_row, b_chd, d);
        __syncthreads();
    }

    float* ssum = (float*)smb;
    float* ssq  = ssum + HH;
    if (do_stats && t < 2 * HH) ssum[t] = 0.f;
    __syncthreads();

    float s_acc[4][2], q_acc[4][2];
#pragma unroll
    for (int nt = 0; nt < 4; nt++) { s_acc[nt][0] = s_acc[nt][1] = 0.f; q_acc[nt][0] = q_acc[nt][1] = 0.f; }

#pragma unroll
    for (int mt = 0; mt < 2; mt++) {
        int r_up = row0 + m0 + mt * 16 + g;
        int r_dn = r_up + 8;
#pragma unroll
        for (int nt = 0; nt < 4; nt++) {
            int cc = n0 + nt * 8 + tid4 * 2;
            float b0 = bias[cc], b1 = bias[cc + 1];
            if (r_up < NN) {
                float v0 = d[mt][nt][0] + b0, v1 = d[mt][nt][1] + b1;
                *(float2*)&zout[(size_t)r_up * HH + cc] = make_float2(v0, v1);
                s_acc[nt][0] += v0; q_acc[nt][0] = fmaf(v0, v0, q_acc[nt][0]);
                s_acc[nt][1] += v1; q_acc[nt][1] = fmaf(v1, v1, q_acc[nt][1]);
            }
            if (r_dn < NN) {
                float v2 = d[mt][nt][2] + b0, v3 = d[mt][nt][3] + b1;
                *(float2*)&zout[(size_t)r_dn * HH + cc] = make_float2(v2, v3);
                s_acc[nt][0] += v2; q_acc[nt][0] = fmaf(v2, v2, q_acc[nt][0]);
                s_acc[nt][1] += v3; q_acc[nt][1] = fmaf(v3, v3, q_acc[nt][1]);
            }
        }
    }

    if (do_stats) {
#pragma unroll
        for (int nt = 0; nt < 4; nt++)
#pragma unroll
            for (int j = 0; j < 2; j++) {
                float sv = s_acc[nt][j], qv = q_acc[nt][j];
                sv += __shfl_down_sync(0xFFFFFFFFu, sv, 16);
                qv += __shfl_down_sync(0xFFFFFFFFu, qv, 16);
                sv += __shfl_down_sync(0xFFFFFFFFu, sv, 8);
                qv += __shfl_down_sync(0xFFFFFFFFu, qv, 8);
                sv += __shfl_down_sync(0xFFFFFFFFu, sv, 4);
                qv += __shfl_down_sync(0xFFFFFFFFu, qv, 4);
                if (g == 0) {
                    int cc = n0 + nt * 8 + tid4 * 2 + j;
                    atomicAdd(&ssum[cc], sv);
                    atomicAdd(&ssq[cc], qv);
                }
            }
        __syncthreads();
        if (t < HH) {
            atomicAdd(&g_bnsum[(size_t)stats_layer * HH + t], ssum[t]);
            atomicAdd(&g_bnsq[(size_t)stats_layer * HH + t], ssq[t]);
        }
    }
}

// ---------------- decoder ----------------
__global__ void k_dec(const float* __restrict__ z, const float* __restrict__ dW,
                      const float* __restrict__ db, float* __restrict__ out) {
    __shared__ float W[HH * OUTF];
    for (int i = threadIdx.x; i < HH * OUTF; i += blockDim.x) W[i] = dW[i];
    __syncthreads();
    int w = (blockIdx.x * blockDim.x + threadIdx.x) >> 5;
    int lane = threadIdx.x & 31;
    if (w >= NN) return;
    float4 zv = *(const float4*)&z[(size_t)w * HH + lane * 4];
    int h = lane * 4;
    float o0 = zv.x * W[h * 4 + 0] + zv.y * W[(h + 1) * 4 + 0] + zv.z * W[(h + 2) * 4 + 0] + zv.w * W[(h + 3) * 4 + 0];
    float o1 = zv.x * W[h * 4 + 1] + zv.y * W[(h + 1) * 4 + 1] + zv.z * W[(h + 2) * 4 + 1] + zv.w * W[(h + 3) * 4 + 1];
    float o2 = zv.x * W[h * 4 + 2] + zv.y * W[(h + 1) * 4 + 2] + zv.z * W[(h + 2) * 4 + 2] + zv.w * W[(h + 3) * 4 + 2];
    float o3 = zv.x * W[h * 4 + 3] + zv.y * W[(h + 1) * 4 + 3] + zv.z * W[(h + 2) * 4 + 3] + zv.w * W[(h + 3) * 4 + 3];
#pragma unroll
    for (int d = 16; d; d >>= 1) {
        o0 += __shfl_down_sync(0xFFFFFFFFu, o0, d);
        o1 += __shfl_down_sync(0xFFFFFFFFu, o1, d);
        o2 += __shfl_down_sync(0xFFFFFFFFu, o2, d);
        o3 += __shfl_down_sync(0xFFFFFFFFu, o3, d);
    }
    if (lane == 0) {
        float4 r;
        r.x = o0 + db[0]; r.y = o1 + db[1]; r.z = o2 + db[2]; r.w = o3 + db[3];
        *(float4*)&out[w * 4] = r;
    }
}

// ---------------- launch ----------------
extern "C" void kernel_launch(void* const* d_in, const int* in_sizes, int n_in,
                              void* d_out, int out_size) {
    const float* x      = (const float*)d_in[0];
    const float* enc_W  = (const float*)d_in[1];
    const float* enc_b  = (const float*)d_in[2];
    const float* Wl     = (const float*)d_in[3];
    const float* Wr     = (const float*)d_in[4];
    const float* b      = (const float*)d_in[5];
    const float* bng    = (const float*)d_in[6];
    const float* bnb    = (const float*)d_in[7];
    const float* dec_W  = (const float*)d_in[8];
    const float* dec_b  = (const float*)d_in[9];
    const void*  ei     = d_in[10];
    float* out = (float*)d_out;

    float *zA, *zB;
    __nv_bfloat16 *Wth, *Wtl;
    void* p;
    cudaGetSymbolAddress(&p, g_zA);  zA  = (float*)p;
    cudaGetSymbolAddress(&p, g_zB);  zB  = (float*)p;
    cudaGetSymbolAddress(&p, g_Wth); Wth = (__nv_bfloat16*)p;
    cudaGetSymbolAddress(&p, g_Wtl); Wtl = (__nv_bfloat16*)p;
    void* pdeg;
    cudaGetSymbolAddress(&pdeg, g_deg);

    cudaFuncSetAttribute(k_gemm_mma, cudaFuncAttributeMaxDynamicSharedMemorySize, GEMM_SMEM);

    const int TB = 256;
    const int egrid = (EE + TB - 1) / TB;

    // CSR build + W conversion
    k_detect<<<1, 32>>>((const int*)ei);
    cudaMemsetAsync(pdeg, 0, NN * sizeof(int));
    k_degree<<<egrid, TB>>>(ei);
    k_scan1<<<(NN + 1023) / 1024, 1024>>>();
    k_scan2<<<1, 32>>>((NN + 1023) / 1024);
    k_scan3<<<(NN + TB - 1) / TB, TB>>>();
    k_scatter<<<egrid, TB>>>(ei);
    k_wconv<<<(2 * NL * HH * HH + TB - 1) / TB, TB>>>(Wl, Wr);

    k_enc<<<(NN * HH + TB - 1) / TB, TB>>>(x, enc_W, enc_b, zA);

    float* zin = zA;
    float* zout = zB;
    for (int i = 0; i < NL; i++) {
        // k_agg: inline BN finalize (layer i-1 stats) + gather + own-row split
        k_agg<<<(NN * 32 + TB - 1) / TB, TB>>>(zin, i,
                bng + (size_t)(i > 0 ? i - 1 : 0) * HH,
                bnb + (size_t)(i > 0 ? i - 1 : 0) * HH);
        k_gemm_mma<<<NTILES, 512, GEMM_SMEM>>>(
            Wth + (size_t)(2 * i + 0) * HH * HH, Wtl + (size_t)(2 * i + 0) * HH * HH,
            Wth + (size_t)(2 * i + 1) * HH * HH, Wtl + (size_t)(2 * i + 1) * HH * HH,
            b + (size_t)i * HH, zout, (i < NL - 1) ? i : -1);
        float* tmp = zin; zin = zout; zout = tmp;
    }

    k_dec<<<(NN * 32 + TB - 1) / TB, TB>>>(zin, dec_W, dec_b, out);
}

// round 15
// speedup vs baseline: 1.5847x; 1.0035x over previous
#include <cuda_runtime.h>
#include <cuda_bf16.h>
#include <math.h>
#include <stdint.h>

#define NN   50000
#define EE   600000
#define HH   128
#define INF  7
#define OUTF 4
#define NL   4
#define MT   128
#define NTILES ((NN + MT - 1) / MT)

// ---------------- scratch ----------------
__device__ float g_zA[NN * HH];
__device__ float g_zB[NN * HH];
__device__ __nv_bfloat16 g_aggh[NN * HH];
__device__ __nv_bfloat16 g_aggl[NN * HH];
__device__ __nv_bfloat16 g_zh[NN * HH];
__device__ __nv_bfloat16 g_zl[NN * HH];
__device__ __nv_bfloat16 g_Wth[2 * NL * HH * HH];   // [layer*2+which][n][k] (transposed)
__device__ __nv_bfloat16 g_Wtl[2 * NL * HH * HH];
__device__ int   g_deg[NN];
__device__ int   g_scan[NN];
__device__ int   g_rowptr[NN + 1];
__device__ int   g_fill[NN];
__device__ int   g_col[EE];
__device__ float g_invdeg[NN];
__device__ int   g_bsum[64];
__device__ int   g_boff[64];
__device__ float g_bnsum[(NL - 1) * HH];   // per-layer stat buffers
__device__ float g_bnsq[(NL - 1) * HH];
__device__ float g_scale[HH];
__device__ float g_shift[HH];

__device__ __forceinline__ uint32_t smem_u32(const void* p) {
    uint32_t a;
    asm("{ .reg .u64 t; cvta.to.shared.u64 t, %1; cvt.u32.u64 %0, t; }" : "=r"(a) : "l"(p));
    return a;
}

// ---------------- warp-level tensor ops (baseline PTX, sm_80+) ----------------
__device__ __forceinline__ void ldsm4(uint32_t* r, uint32_t addr) {
    asm volatile("ldmatrix.sync.aligned.m8n8.x4.shared.b16 {%0,%1,%2,%3}, [%4];"
        : "=r"(r[0]), "=r"(r[1]), "=r"(r[2]), "=r"(r[3]) : "r"(addr));
}
__device__ __forceinline__ void mma16816(float* d, const uint32_t* a, const uint32_t* b) {
    asm volatile("mma.sync.aligned.m16n8k16.row.col.f32.bf16.bf16.f32 "
        "{%0,%1,%2,%3}, {%4,%5,%6,%7}, {%8,%9}, {%0,%1,%2,%3};"
        : "+f"(d[0]), "+f"(d[1]), "+f"(d[2]), "+f"(d[3])
        : "r"(a[0]), "r"(a[1]), "r"(a[2]), "r"(a[3]), "r"(b[0]), "r"(b[1]));
}

// ---------------- edge-index helpers (per-block dtype detection) --------------
__device__ __forceinline__ int clampN(int v) {
    v = v < 0 ? 0 : v;
    return v >= NN ? NN - 1 : v;
}
// int64 little-endian indices < 2^31 have zero odd words; detect per block.
__device__ __forceinline__ int detect64_block(const int* ei32, int* s64) {
    if (threadIdx.x == 0) {
        int z = 0;
#pragma unroll
        for (int i = 0; i < 16; i++) z |= ei32[2 * i + 1];
        *s64 = (z == 0) ? 1 : 0;
    }
    __syncthreads();
    return *s64;
}

// ---------------- CSR build ----------------
__global__ void k_degree(const int* __restrict__ ei32) {
    __shared__ int s64;
    int is64 = detect64_block(ei32, &s64);
    int e = blockIdx.x * blockDim.x + threadIdx.x;
    if (e < EE) {
        int dst = is64 ? (int)((const long long*)ei32)[EE + e] : ei32[EE + e];
        atomicAdd(&g_deg[clampN(dst)], 1);
    }
}
__global__ void k_scan1() {
    __shared__ int wsum[32];
    int i = blockIdx.x * 1024 + threadIdx.x;
    int v = (i < NN) ? g_deg[i] : 0;
    int lane = threadIdx.x & 31, wid = threadIdx.x >> 5;
    int x = v;
#pragma unroll
    for (int d = 1; d < 32; d <<= 1) {
        int y = __shfl_up_sync(0xFFFFFFFFu, x, d);
        if (lane >= d) x += y;
    }
    if (lane == 31) wsum[wid] = x;
    __syncthreads();
    if (wid == 0) {
        int s = wsum[lane];
#pragma unroll
        for (int d = 1; d < 32; d <<= 1) {
            int y = __shfl_up_sync(0xFFFFFFFFu, s, d);
            if (lane >= d) s += y;
        }
        wsum[lane] = s;
    }
    __syncthreads();
    int off = (wid > 0) ? wsum[wid - 1] : 0;
    int incl = x + off;
    if (i < NN) g_scan[i] = incl;
    if (threadIdx.x == 1023) g_bsum[blockIdx.x] = incl;
}
__global__ void k_scan2(int nblk) {
    int lane = threadIdx.x & 31;
    int i0 = 2 * lane, i1 = 2 * lane + 1;
    int a = (i0 < nblk) ? g_bsum[i0] : 0;
    int b = (i1 < nblk) ? g_bsum[i1] : 0;
    int s = a + b;
    int x = s;
#pragma unroll
    for (int d = 1; d < 32; d <<= 1) {
        int y = __shfl_up_sync(0xFFFFFFFFu, x, d);
        if (lane >= d) x += y;
    }
    int excl = x - s;
    if (i0 < nblk) g_boff[i0] = excl;
    if (i1 < nblk) g_boff[i1] = excl + a;
}
__global__ void k_scan3() {
    int i = blockIdx.x * blockDim.x + threadIdx.x;
    if (i < NN) {
        g_rowptr[i + 1] = g_scan[i] + g_boff[i >> 10];
        if (i == 0) g_rowptr[0] = 0;
        g_fill[i] = 0;
        int d = g_deg[i];
        g_invdeg[i] = 1.0f / (float)(d > 1 ? d : 1);
    }
}
__global__ void k_scatter(const int* __restrict__ ei32) {
    __shared__ int s64;
    int is64 = detect64_block(ei32, &s64);
    int e = blockIdx.x * blockDim.x + threadIdx.x;
    if (e < EE) {
        int dst, src;
        if (is64) {
            dst = (int)((const long long*)ei32)[EE + e];
            src = (int)((const long long*)ei32)[e];
        } else {
            dst = ei32[EE + e];
            src = ei32[e];
        }
        dst = clampN(dst); src = clampN(src);
        int p = g_rowptr[dst] + atomicAdd(&g_fill[dst], 1);
        g_col[p] = src;
    }
}

// ---------------- W transpose + bf16 split (once per launch) ----------------
__global__ void k_wconv(const float* __restrict__ Wl, const float* __restrict__ Wr) {
    int idx = blockIdx.x * blockDim.x + threadIdx.x;
    if (idx >= 2 * NL * HH * HH) return;
    int m2 = idx / (HH * HH);
    int rem = idx - m2 * (HH * HH);
    int n = rem >> 7, k = rem & 127;
    int layer = m2 >> 1;
    const float* src = (m2 & 1) ? Wr : Wl;
    float v = src[layer * HH * HH + k * HH + n];      // B[n][k] = W[k][n]
    __nv_bfloat16 hi = __float2bfloat16_rn(v);
    __nv_bfloat16 lo = __float2bfloat16_rn(v - __bfloat162float(hi));
    g_Wth[m2 * HH * HH + n * HH + k] = hi;
    g_Wtl[m2 * HH * HH + n * HH + k] = lo;
}

// ---------------- encoder (fp32 z; zeroes per-layer BN stat buffers) ---------
__global__ void k_enc(const float* __restrict__ x, const float* __restrict__ eW,
                      const float* __restrict__ eb, float* __restrict__ z) {
    __shared__ float W[INF * HH];
    int gid = blockIdx.x * blockDim.x + threadIdx.x;
    if (gid < (NL - 1) * HH) { g_bnsum[gid] = 0.f; g_bnsq[gid] = 0.f; }
    for (int i = threadIdx.x; i < INF * HH; i += blockDim.x) W[i] = eW[i];
    __syncthreads();
    if (gid >= NN * HH) return;
    int n = gid >> 7, h = gid & 127;
    float s = eb[h];
    const float* xr = x + n * INF;
#pragma unroll
    for (int k = 0; k < INF; k++) s = fmaf(xr[k], W[k * HH + h], s);
    z[gid] = s;
}

// ---------------- BatchNorm finalize (per BN layer, precomputes scale/shift) --
__global__ void k_bnfin(int layer, const float* __restrict__ gamma,
                        const float* __restrict__ beta) {
    int h = threadIdx.x;
    float inv = 1.0f / (float)NN;
    float mu = g_bnsum[(size_t)layer * HH + h] * inv;
    float var = g_bnsq[(size_t)layer * HH + h] * inv - mu * mu;
    float sc = gamma[h] * rsqrtf(var + 1e-5f);
    g_scale[h] = sc;
    g_shift[h] = beta[h] - mu * sc;
}

// ---------------- aggregation: fused BN/ReLU gather (MLP-4 unrolled) +
//                  own-row bf16 split ----------------------------------------
__device__ __forceinline__ float4 bn_relu(float4 v, float4 sc, float4 sh, int on) {
    if (on) {
        v.x = fmaxf(fmaf(v.x, sc.x, sh.x), 0.f);
        v.y = fmaxf(fmaf(v.y, sc.y, sh.y), 0.f);
        v.z = fmaxf(fmaf(v.z, sc.z, sh.z), 0.f);
        v.w = fmaxf(fmaf(v.w, sc.w, sh.w), 0.f);
    }
    return v;
}
__device__ __forceinline__ void split_store(__nv_bfloat16* dh, __nv_bfloat16* dl,
                                            size_t off, float4 v) {
    __nv_bfloat162 hA = __floats2bfloat162_rn(v.x, v.y);
    __nv_bfloat162 hB = __floats2bfloat162_rn(v.z, v.w);
    __nv_bfloat162 lA = __floats2bfloat162_rn(v.x - __low2float(hA), v.y - __high2float(hA));
    __nv_bfloat162 lB = __floats2bfloat162_rn(v.z - __low2float(hB), v.w - __high2float(hB));
    uint2 ph, pl;
    ph.x = *(uint32_t*)&hA; ph.y = *(uint32_t*)&hB;
    pl.x = *(uint32_t*)&lA; pl.y = *(uint32_t*)&lB;
    *(uint2*)(dh + off) = ph;
    *(uint2*)(dl + off) = pl;
}

__global__ void k_agg(const float* __restrict__ zin, int apply_bn) {
    int w = (blockIdx.x * blockDim.x + threadIdx.x) >> 5;
    int lane = threadIdx.x & 31;
    if (w >= NN) return;
    float4 sc = make_float4(1.f, 1.f, 1.f, 1.f);
    float4 sh = make_float4(0.f, 0.f, 0.f, 0.f);
    if (apply_bn) {
        sc = ((const float4*)g_scale)[lane];
        sh = ((const float4*)g_shift)[lane];
    }

    // own-row: BN+ReLU then bf16 hi/lo split for the GEMM z operand
    {
        float4 v = bn_relu(*(const float4*)&zin[(size_t)w * HH + lane * 4], sc, sh, apply_bn);
        split_store(g_zh, g_zl, (size_t)w * HH + lane * 4, v);
    }

    int beg = g_rowptr[w], end = g_rowptr[w + 1];
    float4 acc = make_float4(0.f, 0.f, 0.f, 0.f);
    int j = beg;
    // 4-way batched gather: 4 index loads then 4 row loads in flight (MLP>=4)
    for (; j + 4 <= end; j += 4) {
        int s0 = g_col[j], s1 = g_col[j + 1], s2 = g_col[j + 2], s3 = g_col[j + 3];
        float4 v0 = *(const float4*)&zin[(size_t)s0 * HH + lane * 4];
        float4 v1 = *(const float4*)&zin[(size_t)s1 * HH + lane * 4];
        float4 v2 = *(const float4*)&zin[(size_t)s2 * HH + lane * 4];
        float4 v3 = *(const float4*)&zin[(size_t)s3 * HH + lane * 4];
        v0 = bn_relu(v0, sc, sh, apply_bn);
        v1 = bn_relu(v1, sc, sh, apply_bn);
        v2 = bn_relu(v2, sc, sh, apply_bn);
        v3 = bn_relu(v3, sc, sh, apply_bn);
        acc.x += v0.x; acc.y += v0.y; acc.z += v0.z; acc.w += v0.w;
        acc.x += v1.x; acc.y += v1.y; acc.z += v1.z; acc.w += v1.w;
        acc.x += v2.x; acc.y += v2.y; acc.z += v2.z; acc.w += v2.w;
        acc.x += v3.x; acc.y += v3.y; acc.z += v3.z; acc.w += v3.w;
    }
    for (; j < end; j++) {
        int s = g_col[j];
        float4 v = bn_relu(*(const float4*)&zin[(size_t)s * HH + lane * 4], sc, sh, apply_bn);
        acc.x += v.x; acc.y += v.y; acc.z += v.z; acc.w += v.w;
    }
    float id = g_invdeg[w];
    acc.x *= id; acc.y *= id; acc.z *= id; acc.w *= id;
    split_store(g_aggh, g_aggl, (size_t)w * HH + lane * 4, acc);
}

// ---------------- HMMA GEMM: zout = [agg|z] @ [Wl;Wr] + b  (K=256 pipelined) --
// R12 config: 512 threads, warp tile 32x32, 4 K-chunks of 64,
// cp.async double buffering, XOR swizzle, 1 CTA/SM. Fused BN stats epilogue.
#define CH_TILE 16384
#define OFF_AH  0
#define OFF_AL  32768
#define OFF_BH  65536
#define OFF_BL  98304
#define GEMM_SMEM 131072

__device__ __forceinline__ void cpa16(uint32_t dst, const void* src, uint32_t zf) {
    asm volatile("cp.async.cg.shared.global [%0], [%1], 16, %2;"
        :: "r"(dst), "l"(src), "r"(zf) : "memory");
}
__device__ __forceinline__ void cpa16u(uint32_t dst, const void* src) {
    asm volatile("cp.async.cg.shared.global [%0], [%1], 16;"
        :: "r"(dst), "l"(src) : "memory");
}

__device__ __forceinline__ void stage_chunk(uint32_t sb, int b,
        const __nv_bfloat16* ah, const __nv_bfloat16* al,
        const __nv_bfloat16* bh, const __nv_bfloat16* bl,
        int colofs, int row0, int t) {
    for (int i = t; i < 1024; i += 512) {
        int row = i >> 3, ch = i & 7;
        uint32_t sw = (uint32_t)(row * 128 + ((ch ^ (row & 7)) * 16));
        int gr = row0 + row;
        uint32_t zf = (gr < NN) ? 16u : 0u;
        size_t ao = (size_t)gr * HH + colofs + ch * 8;
        cpa16(sb + OFF_AH + b * CH_TILE + sw, ah + ao, zf);
        cpa16(sb + OFF_AL + b * CH_TILE + sw, al + ao, zf);
        size_t bo = (size_t)row * HH + colofs + ch * 8;
        cpa16u(sb + OFF_BH + b * CH_TILE + sw, bh + bo);
        cpa16u(sb + OFF_BL + b * CH_TILE + sw, bl + bo);
    }
    asm volatile("cp.async.commit_group;" ::: "memory");
}

__device__ __forceinline__ void compute_chunk(uint32_t sb, int b, int m0, int n0,
        int a_row, int a_chd, int b_row, int b_chd, float d[2][4][4]) {
    uint32_t aH = sb + OFF_AH + b * CH_TILE;
    uint32_t aL = sb + OFF_AL + b * CH_TILE;
    uint32_t bH = sb + OFF_BH + b * CH_TILE;
    uint32_t bL = sb + OFF_BL + b * CH_TILE;
#pragma unroll
    for (int ks = 0; ks < 4; ks++) {
        int c = ks * 2;
        uint32_t ah[2][4], al[2][4], bh[2][4], bl[2][4];
#pragma unroll
        for (int mt = 0; mt < 2; mt++) {
            int row = m0 + mt * 16 + a_row;
            int ch = c + a_chd;
            uint32_t o = (uint32_t)(row * 128 + ((ch ^ (row & 7)) * 16));
            ldsm4(ah[mt], aH + o);
            ldsm4(al[mt], aL + o);
        }
#pragma unroll
        for (int np = 0; np < 2; np++) {
            int row = n0 + np * 16 + b_row;
            int ch = c + b_chd;
            uint32_t o = (uint32_t)(row * 128 + ((ch ^ (row & 7)) * 16));
            ldsm4(bh[np], bH + o);
            ldsm4(bl[np], bL + o);
        }
#pragma unroll
        for (int mt = 0; mt < 2; mt++)
#pragma unroll
            for (int nt = 0; nt < 4; nt++) {
                const uint32_t* fh = &bh[nt >> 1][(nt & 1) * 2];
                const uint32_t* fl = &bl[nt >> 1][(nt & 1) * 2];
                mma16816(d[mt][nt], ah[mt], fh);   // hi*hi
                mma16816(d[mt][nt], ah[mt], fl);   // hi*lo
                mma16816(d[mt][nt], al[mt], fh);   // lo*hi
            }
    }
}

__global__ void __launch_bounds__(512, 1)
k_gemm_mma(const __nv_bfloat16* __restrict__ wlh, const __nv_bfloat16* __restrict__ wll,
           const __nv_bfloat16* __restrict__ wrh, const __nv_bfloat16* __restrict__ wrl,
           const float* __restrict__ bias, float* __restrict__ zout, int stats_layer) {
    extern __shared__ char smb[];
    uint32_t sb = smem_u32(smb);
    const int t = threadIdx.x, wid = t >> 5, lane = t & 31;
    const int m0 = (wid & 3) * 32;
    const int n0 = (wid >> 2) * 32;
    const int row0 = blockIdx.x * MT;
    const int g = lane >> 2, tid4 = lane & 3;
    const int do_stats = (stats_layer >= 0);

    const int a_row = lane & 15, a_chd = lane >> 4;
    const int b_row = (lane & 7) + ((lane >> 4) << 3), b_chd = (lane >> 3) & 1;

    float d[2][4][4];
#pragma unroll
    for (int mt = 0; mt < 2; mt++)
#pragma unroll
        for (int nt = 0; nt < 4; nt++)
#pragma unroll
            for (int j = 0; j < 4; j++) d[mt][nt][j] = 0.f;

    const __nv_bfloat16* Ah[4] = {g_aggh, g_aggh, g_zh, g_zh};
    const __nv_bfloat16* Al[4] = {g_aggl, g_aggl, g_zl, g_zl};
    const __nv_bfloat16* Bh[4] = {wlh, wlh, wrh, wrh};
    const __nv_bfloat16* Bl[4] = {wll, wll, wrl, wrl};

    stage_chunk(sb, 0, Ah[0], Al[0], Bh[0], Bl[0], 0, row0, t);
#pragma unroll
    for (int c = 0; c < 4; c++) {
        if (c + 1 < 4) {
            stage_chunk(sb, (c + 1) & 1, Ah[c + 1], Al[c + 1], Bh[c + 1], Bl[c + 1],
                        ((c + 1) & 1) * 64, row0, t);
            asm volatile("cp.async.wait_group 1;" ::: "memory");
        } else {
            asm volatile("cp.async.wait_group 0;" ::: "memory");
        }
        __syncthreads();
        compute_chunk(sb, c & 1, m0, n0, a_row, a_chd, b_row, b_chd, d);
        __syncthreads();
    }

    float* ssum = (float*)smb;
    float* ssq  = ssum + HH;
    if (do_stats && t < 2 * HH) ssum[t] = 0.f;
    __syncthreads();

    float s_acc[4][2], q_acc[4][2];
#pragma unroll
    for (int nt = 0; nt < 4; nt++) { s_acc[nt][0] = s_acc[nt][1] = 0.f; q_acc[nt][0] = q_acc[nt][1] = 0.f; }

#pragma unroll
    for (int mt = 0; mt < 2; mt++) {
        int r_up = row0 + m0 + mt * 16 + g;
        int r_dn = r_up + 8;
#pragma unroll
        for (int nt = 0; nt < 4; nt++) {
            int cc = n0 + nt * 8 + tid4 * 2;
            float b0 = bias[cc], b1 = bias[cc + 1];
            if (r_up < NN) {
                float v0 = d[mt][nt][0] + b0, v1 = d[mt][nt][1] + b1;
                *(float2*)&zout[(size_t)r_up * HH + cc] = make_float2(v0, v1);
                s_acc[nt][0] += v0; q_acc[nt][0] = fmaf(v0, v0, q_acc[nt][0]);
                s_acc[nt][1] += v1; q_acc[nt][1] = fmaf(v1, v1, q_acc[nt][1]);
            }
            if (r_dn < NN) {
                float v2 = d[mt][nt][2] + b0, v3 = d[mt][nt][3] + b1;
                *(float2*)&zout[(size_t)r_dn * HH + cc] = make_float2(v2, v3);
                s_acc[nt][0] += v2; q_acc[nt][0] = fmaf(v2, v2, q_acc[nt][0]);
                s_acc[nt][1] += v3; q_acc[nt][1] = fmaf(v3, v3, q_acc[nt][1]);
            }
        }
    }

    if (do_stats) {
#pragma unroll
        for (int nt = 0; nt < 4; nt++)
#pragma unroll
            for (int j = 0; j < 2; j++) {
                float sv = s_acc[nt][j], qv = q_acc[nt][j];
                sv += __shfl_down_sync(0xFFFFFFFFu, sv, 16);
                qv += __shfl_down_sync(0xFFFFFFFFu, qv, 16);
                sv += __shfl_down_sync(0xFFFFFFFFu, sv, 8);
                qv += __shfl_down_sync(0xFFFFFFFFu, qv, 8);
                sv += __shfl_down_sync(0xFFFFFFFFu, sv, 4);
                qv += __shfl_down_sync(0xFFFFFFFFu, qv, 4);
                if (g == 0) {
                    int cc = n0 + nt * 8 + tid4 * 2 + j;
                    atomicAdd(&ssum[cc], sv);
                    atomicAdd(&ssq[cc], qv);
                }
            }
        __syncthreads();
        if (t < HH) {
            atomicAdd(&g_bnsum[(size_t)stats_layer * HH + t], ssum[t]);
            atomicAdd(&g_bnsq[(size_t)stats_layer * HH + t], ssq[t]);
        }
    }
}

// ---------------- decoder ----------------
__global__ void k_dec(const float* __restrict__ z, const float* __restrict__ dW,
                      const float* __restrict__ db, float* __restrict__ out) {
    __shared__ float W[HH * OUTF];
    for (int i = threadIdx.x; i < HH * OUTF; i += blockDim.x) W[i] = dW[i];
    __syncthreads();
    int w = (blockIdx.x * blockDim.x + threadIdx.x) >> 5;
    int lane = threadIdx.x & 31;
    if (w >= NN) return;
    float4 zv = *(const float4*)&z[(size_t)w * HH + lane * 4];
    int h = lane * 4;
    float o0 = zv.x * W[h * 4 + 0] + zv.y * W[(h + 1) * 4 + 0] + zv.z * W[(h + 2) * 4 + 0] + zv.w * W[(h + 3) * 4 + 0];
    float o1 = zv.x * W[h * 4 + 1] + zv.y * W[(h + 1) * 4 + 1] + zv.z * W[(h + 2) * 4 + 1] + zv.w * W[(h + 3) * 4 + 1];
    float o2 = zv.x * W[h * 4 + 2] + zv.y * W[(h + 1) * 4 + 2] + zv.z * W[(h + 2) * 4 + 2] + zv.w * W[(h + 3) * 4 + 2];
    float o3 = zv.x * W[h * 4 + 3] + zv.y * W[(h + 1) * 4 + 3] + zv.z * W[(h + 2) * 4 + 3] + zv.w * W[(h + 3) * 4 + 3];
#pragma unroll
    for (int d = 16; d; d >>= 1) {
        o0 += __shfl_down_sync(0xFFFFFFFFu, o0, d);
        o1 += __shfl_down_sync(0xFFFFFFFFu, o1, d);
        o2 += __shfl_down_sync(0xFFFFFFFFu, o2, d);
        o3 += __shfl_down_sync(0xFFFFFFFFu, o3, d);
    }
    if (lane == 0) {
        float4 r;
        r.x = o0 + db[0]; r.y = o1 + db[1]; r.z = o2 + db[2]; r.w = o3 + db[3];
        *(float4*)&out[w * 4] = r;
    }
}

// ---------------- launch ----------------
extern "C" void kernel_launch(void* const* d_in, const int* in_sizes, int n_in,
                              void* d_out, int out_size) {
    const float* x      = (const float*)d_in[0];
    const float* enc_W  = (const float*)d_in[1];
    const float* enc_b  = (const float*)d_in[2];
    const float* Wl     = (const float*)d_in[3];
    const float* Wr     = (const float*)d_in[4];
    const float* b      = (const float*)d_in[5];
    const float* bng    = (const float*)d_in[6];
    const float* bnb    = (const float*)d_in[7];
    const float* dec_W  = (const float*)d_in[8];
    const float* dec_b  = (const float*)d_in[9];
    const int*   ei     = (const int*)d_in[10];
    float* out = (float*)d_out;

    float *zA, *zB;
    __nv_bfloat16 *Wth, *Wtl;
    void* p;
    cudaGetSymbolAddress(&p, g_zA);  zA  = (float*)p;
    cudaGetSymbolAddress(&p, g_zB);  zB  = (float*)p;
    cudaGetSymbolAddress(&p, g_Wth); Wth = (__nv_bfloat16*)p;
    cudaGetSymbolAddress(&p, g_Wtl); Wtl = (__nv_bfloat16*)p;
    void* pdeg;
    cudaGetSymbolAddress(&pdeg, g_deg);

    cudaFuncSetAttribute(k_gemm_mma, cudaFuncAttributeMaxDynamicSharedMemorySize, GEMM_SMEM);

    const int TB = 256;
    const int egrid = (EE + TB - 1) / TB;

    // CSR build + W conversion
    cudaMemsetAsync(pdeg, 0, NN * sizeof(int));
    k_degree<<<egrid, TB>>>(ei);
    k_scan1<<<(NN + 1023) / 1024, 1024>>>();
    k_scan2<<<1, 32>>>((NN + 1023) / 1024);
    k_scan3<<<(NN + TB - 1) / TB, TB>>>();
    k_scatter<<<egrid, TB>>>(ei);
    k_wconv<<<(2 * NL * HH * HH + TB - 1) / TB, TB>>>(Wl, Wr);

    k_enc<<<(NN * HH + TB - 1) / TB, TB>>>(x, enc_W, enc_b, zA);

    float* zin = zA;
    float* zout = zB;
    for (int i = 0; i < NL; i++) {
        if (i > 0)
            k_bnfin<<<1, HH>>>(i - 1, bng + (size_t)(i - 1) * HH, bnb + (size_t)(i - 1) * HH);
        k_agg<<<(NN * 32 + TB - 1) / TB, TB>>>(zin, i > 0);
        k_gemm_mma<<<NTILES, 512, GEMM_SMEM>>>(
            Wth + (size_t)(2 * i + 0) * HH * HH, Wtl + (size_t)(2 * i + 0) * HH * HH,
            Wth + (size_t)(2 * i + 1) * HH * HH, Wtl + (size_t)(2 * i + 1) * HH * HH,
            b + (size_t)i * HH, zout, (i < NL - 1) ? i : -1);
        float* tmp = zin; zin = zout; zout = tmp;
    }

    k_dec<<<(NN * 32 + TB - 1) / TB, TB>>>(zin, dec_W, dec_b, out);
}

// round 16
// speedup vs baseline: 1.7002x; 1.0729x over previous
#include <cuda_runtime.h>
#include <cuda_bf16.h>
#include <math.h>
#include <stdint.h>

#define NN   50000
#define EE   600000
#define HH   128
#define INF  7
#define OUTF 4
#define NL   4
#define MT   128
#define NTILES ((NN + MT - 1) / MT)

// ---------------- scratch ----------------
__device__ float g_zA[NN * HH];
__device__ float g_zB[NN * HH];
__device__ __nv_bfloat16 g_aggh[NN * HH];
__device__ __nv_bfloat16 g_aggl[NN * HH];
__device__ __nv_bfloat16 g_zh[NN * HH];
__device__ __nv_bfloat16 g_zl[NN * HH];
__device__ __nv_bfloat16 g_Wth[2 * NL * HH * HH];   // [layer*2+which][n][k] (transposed)
__device__ __nv_bfloat16 g_Wtl[2 * NL * HH * HH];
__device__ int   g_deg[NN];
__device__ int   g_scan[NN];
__device__ int   g_rowptr[NN + 1];
__device__ int   g_fill[NN];
__device__ int   g_col[EE];
__device__ float g_invdeg[NN];
__device__ int   g_bsum[64];
__device__ float g_bnsum[(NL - 1) * HH];   // per-layer stat buffers
__device__ float g_bnsq[(NL - 1) * HH];
__device__ float g_scale[HH];
__device__ float g_shift[HH];

__device__ __forceinline__ uint32_t smem_u32(const void* p) {
    uint32_t a;
    asm("{ .reg .u64 t; cvta.to.shared.u64 t, %1; cvt.u32.u64 %0, t; }" : "=r"(a) : "l"(p));
    return a;
}

// ---------------- warp-level tensor ops (baseline PTX, sm_80+) ----------------
__device__ __forceinline__ void ldsm4(uint32_t* r, uint32_t addr) {
    asm volatile("ldmatrix.sync.aligned.m8n8.x4.shared.b16 {%0,%1,%2,%3}, [%4];"
        : "=r"(r[0]), "=r"(r[1]), "=r"(r[2]), "=r"(r[3]) : "r"(addr));
}
__device__ __forceinline__ void mma16816(float* d, const uint32_t* a, const uint32_t* b) {
    asm volatile("mma.sync.aligned.m16n8k16.row.col.f32.bf16.bf16.f32 "
        "{%0,%1,%2,%3}, {%4,%5,%6,%7}, {%8,%9}, {%0,%1,%2,%3};"
        : "+f"(d[0]), "+f"(d[1]), "+f"(d[2]), "+f"(d[3])
        : "r"(a[0]), "r"(a[1]), "r"(a[2]), "r"(a[3]), "r"(b[0]), "r"(b[1]));
}

// ---------------- edge-index helpers (per-block dtype detection) --------------
__device__ __forceinline__ int clampN(int v) {
    v = v < 0 ? 0 : v;
    return v >= NN ? NN - 1 : v;
}
__device__ __forceinline__ int detect64_block(const int* ei32, int* s64) {
    if (threadIdx.x == 0) {
        int z = 0;
#pragma unroll
        for (int i = 0; i < 16; i++) z |= ei32[2 * i + 1];
        *s64 = (z == 0) ? 1 : 0;
    }
    __syncthreads();
    return *s64;
}

// ---------------- CSR build ----------------
__global__ void k_degree(const int* __restrict__ ei32) {
    __shared__ int s64;
    int is64 = detect64_block(ei32, &s64);
    int e = blockIdx.x * blockDim.x + threadIdx.x;
    if (e < EE) {
        int dst = is64 ? (int)((const long long*)ei32)[EE + e] : ei32[EE + e];
        atomicAdd(&g_deg[clampN(dst)], 1);
    }
}
__global__ void k_scan1() {
    __shared__ int wsum[32];
    int i = blockIdx.x * 1024 + threadIdx.x;
    int v = (i < NN) ? g_deg[i] : 0;
    int lane = threadIdx.x & 31, wid = threadIdx.x >> 5;
    int x = v;
#pragma unroll
    for (int d = 1; d < 32; d <<= 1) {
        int y = __shfl_up_sync(0xFFFFFFFFu, x, d);
        if (lane >= d) x += y;
    }
    if (lane == 31) wsum[wid] = x;
    __syncthreads();
    if (wid == 0) {
        int s = wsum[lane];
#pragma unroll
        for (int d = 1; d < 32; d <<= 1) {
            int y = __shfl_up_sync(0xFFFFFFFFu, s, d);
            if (lane >= d) s += y;
        }
        wsum[lane] = s;
    }
    __syncthreads();
    int off = (wid > 0) ? wsum[wid - 1] : 0;
    int incl = x + off;
    if (i < NN) g_scan[i] = incl;
    if (threadIdx.x == 1023) g_bsum[blockIdx.x] = incl;
}
// scan3 with scan2 fused: warp 0 scans the <=64 block sums into smem (redundant
// per block, ~30 cyc), then all threads use the exclusive block offsets.
__global__ void k_scan3(int nblk) {
    __shared__ int boff[64];
    int lane = threadIdx.x & 31;
    if (threadIdx.x < 32) {
        int i0 = 2 * lane, i1 = 2 * lane + 1;
        int a = (i0 < nblk) ? g_bsum[i0] : 0;
        int b = (i1 < nblk) ? g_bsum[i1] : 0;
        int s = a + b;
        int x = s;
#pragma unroll
        for (int d = 1; d < 32; d <<= 1) {
            int y = __shfl_up_sync(0xFFFFFFFFu, x, d);
            if (lane >= d) x += y;
        }
        int excl = x - s;
        boff[i0] = excl;
        boff[i1] = excl + a;
    }
    __syncthreads();
    int i = blockIdx.x * blockDim.x + threadIdx.x;
    if (i < NN) {
        g_rowptr[i + 1] = g_scan[i] + boff[i >> 10];
        if (i == 0) g_rowptr[0] = 0;
        g_fill[i] = 0;
        int d = g_deg[i];
        g_invdeg[i] = 1.0f / (float)(d > 1 ? d : 1);
    }
}
__global__ void k_scatter(const int* __restrict__ ei32) {
    __shared__ int s64;
    int is64 = detect64_block(ei32, &s64);
    int e = blockIdx.x * blockDim.x + threadIdx.x;
    if (e < EE) {
        int dst, src;
        if (is64) {
            dst = (int)((const long long*)ei32)[EE + e];
            src = (int)((const long long*)ei32)[e];
        } else {
            dst = ei32[EE + e];
            src = ei32[e];
        }
        dst = clampN(dst); src = clampN(src);
        int p = g_rowptr[dst] + atomicAdd(&g_fill[dst], 1);
        g_col[p] = src;
    }
}

// ---------------- W transpose + bf16 split (once per launch) ----------------
__global__ void k_wconv(const float* __restrict__ Wl, const float* __restrict__ Wr) {
    int idx = blockIdx.x * blockDim.x + threadIdx.x;
    if (idx >= 2 * NL * HH * HH) return;
    int m2 = idx / (HH * HH);
    int rem = idx - m2 * (HH * HH);
    int n = rem >> 7, k = rem & 127;
    int layer = m2 >> 1;
    const float* src = (m2 & 1) ? Wr : Wl;
    float v = src[layer * HH * HH + k * HH + n];      // B[n][k] = W[k][n]
    __nv_bfloat16 hi = __float2bfloat16_rn(v);
    __nv_bfloat16 lo = __float2bfloat16_rn(v - __bfloat162float(hi));
    g_Wth[m2 * HH * HH + n * HH + k] = hi;
    g_Wtl[m2 * HH * HH + n * HH + k] = lo;
}

// ---------------- split helper ----------------
__device__ __forceinline__ void split_store(__nv_bfloat16* dh, __nv_bfloat16* dl,
                                            size_t off, float4 v) {
    __nv_bfloat162 hA = __floats2bfloat162_rn(v.x, v.y);
    __nv_bfloat162 hB = __floats2bfloat162_rn(v.z, v.w);
    __nv_bfloat162 lA = __floats2bfloat162_rn(v.x - __low2float(hA), v.y - __high2float(hA));
    __nv_bfloat162 lB = __floats2bfloat162_rn(v.z - __low2float(hB), v.w - __high2float(hB));
    uint2 ph, pl;
    ph.x = *(uint32_t*)&hA; ph.y = *(uint32_t*)&hB;
    pl.x = *(uint32_t*)&lA; pl.y = *(uint32_t*)&lB;
    *(uint2*)(dh + off) = ph;
    *(uint2*)(dl + off) = pl;
}

// ---------------- encoder (fp32 z + layer-0 bf16 split; zeroes BN stats) -----
__global__ void k_enc(const float* __restrict__ x, const float* __restrict__ eW,
                      const float* __restrict__ eb, float* __restrict__ z) {
    __shared__ float W[INF * HH];
    int gid = blockIdx.x * blockDim.x + threadIdx.x;
    if (gid < (NL - 1) * HH) { g_bnsum[gid] = 0.f; g_bnsq[gid] = 0.f; }
    for (int i = threadIdx.x; i < INF * HH; i += blockDim.x) W[i] = eW[i];
    __syncthreads();
    if (gid >= NN * HH) return;
    int n = gid >> 7, h = gid & 127;
    float s = eb[h];
    const float* xr = x + n * INF;
#pragma unroll
    for (int k = 0; k < INF; k++) s = fmaf(xr[k], W[k * HH + h], s);
    z[gid] = s;
    __nv_bfloat16 hi = __float2bfloat16_rn(s);
    g_zh[gid] = hi;
    g_zl[gid] = __float2bfloat16_rn(s - __bfloat162float(hi));
}

// ---------------- BatchNorm finalize ----------------
__global__ void k_bnfin(int layer, const float* __restrict__ gamma,
                        const float* __restrict__ beta) {
    int h = threadIdx.x;
    float inv = 1.0f / (float)NN;
    float mu = g_bnsum[(size_t)layer * HH + h] * inv;
    float var = g_bnsq[(size_t)layer * HH + h] * inv - mu * mu;
    float sc = gamma[h] * rsqrtf(var + 1e-5f);
    g_scale[h] = sc;
    g_shift[h] = beta[h] - mu * sc;
}

// ---------------- aggregation: fused BN/ReLU gather + own-row split (BN layers)
__global__ void k_agg(const float* __restrict__ zin, int apply_bn) {
    int w = (blockIdx.x * blockDim.x + threadIdx.x) >> 5;
    int lane = threadIdx.x & 31;
    if (w >= NN) return;
    float4 sc = make_float4(1.f, 1.f, 1.f, 1.f);
    float4 sh = make_float4(0.f, 0.f, 0.f, 0.f);
    if (apply_bn) {
        sc = ((const float4*)g_scale)[lane];
        sh = ((const float4*)g_shift)[lane];
        // own-row: BN+ReLU then bf16 hi/lo split (layer 0 handled by k_enc)
        float4 v = *(const float4*)&zin[(size_t)w * HH + lane * 4];
        v.x = fmaxf(fmaf(v.x, sc.x, sh.x), 0.f);
        v.y = fmaxf(fmaf(v.y, sc.y, sh.y), 0.f);
        v.z = fmaxf(fmaf(v.z, sc.z, sh.z), 0.f);
        v.w = fmaxf(fmaf(v.w, sc.w, sh.w), 0.f);
        split_store(g_zh, g_zl, (size_t)w * HH + lane * 4, v);
    }

    int beg = g_rowptr[w], end = g_rowptr[w + 1];
    float4 acc = make_float4(0.f, 0.f, 0.f, 0.f);
    for (int j = beg; j < end; j++) {
        int s = g_col[j];
        float4 v = *(const float4*)&zin[(size_t)s * HH + lane * 4];
        if (apply_bn) {
            v.x = fmaxf(fmaf(v.x, sc.x, sh.x), 0.f);
            v.y = fmaxf(fmaf(v.y, sc.y, sh.y), 0.f);
            v.z = fmaxf(fmaf(v.z, sc.z, sh.z), 0.f);
            v.w = fmaxf(fmaf(v.w, sc.w, sh.w), 0.f);
        }
        acc.x += v.x; acc.y += v.y; acc.z += v.z; acc.w += v.w;
    }
    float id = g_invdeg[w];
    acc.x *= id; acc.y *= id; acc.z *= id; acc.w *= id;
    split_store(g_aggh, g_aggl, (size_t)w * HH + lane * 4, acc);
}

// ---------------- HMMA GEMM: zout = [agg|z] @ [Wl;Wr] + b  (K=256 pipelined) --
// R12 config: 512 threads, warp tile 32x32, 4 K-chunks of 64,
// cp.async double buffering, XOR swizzle, 1 CTA/SM. Fused BN stats epilogue.
#define CH_TILE 16384
#define OFF_AH  0
#define OFF_AL  32768
#define OFF_BH  65536
#define OFF_BL  98304
#define GEMM_SMEM 131072

__device__ __forceinline__ void cpa16(uint32_t dst, const void* src, uint32_t zf) {
    asm volatile("cp.async.cg.shared.global [%0], [%1], 16, %2;"
        :: "r"(dst), "l"(src), "r"(zf) : "memory");
}
__device__ __forceinline__ void cpa16u(uint32_t dst, const void* src) {
    asm volatile("cp.async.cg.shared.global [%0], [%1], 16;"
        :: "r"(dst), "l"(src) : "memory");
}

__device__ __forceinline__ void stage_chunk(uint32_t sb, int b,
        const __nv_bfloat16* ah, const __nv_bfloat16* al,
        const __nv_bfloat16* bh, const __nv_bfloat16* bl,
        int colofs, int row0, int t) {
    for (int i = t; i < 1024; i += 512) {
        int row = i >> 3, ch = i & 7;
        uint32_t sw = (uint32_t)(row * 128 + ((ch ^ (row & 7)) * 16));
        int gr = row0 + row;
        uint32_t zf = (gr < NN) ? 16u : 0u;
        size_t ao = (size_t)gr * HH + colofs + ch * 8;
        cpa16(sb + OFF_AH + b * CH_TILE + sw, ah + ao, zf);
        cpa16(sb + OFF_AL + b * CH_TILE + sw, al + ao, zf);
        size_t bo = (size_t)row * HH + colofs + ch * 8;
        cpa16u(sb + OFF_BH + b * CH_TILE + sw, bh + bo);
        cpa16u(sb + OFF_BL + b * CH_TILE + sw, bl + bo);
    }
    asm volatile("cp.async.commit_group;" ::: "memory");
}

__device__ __forceinline__ void compute_chunk(uint32_t sb, int b, int m0, int n0,
        int a_row, int a_chd, int b_row, int b_chd, float d[2][4][4]) {
    uint32_t aH = sb + OFF_AH + b * CH_TILE;
    uint32_t aL = sb + OFF_AL + b * CH_TILE;
    uint32_t bH = sb + OFF_BH + b * CH_TILE;
    uint32_t bL = sb + OFF_BL + b * CH_TILE;
#pragma unroll
    for (int ks = 0; ks < 4; ks++) {
        int c = ks * 2;
        uint32_t ah[2][4], al[2][4], bh[2][4], bl[2][4];
#pragma unroll
        for (int mt = 0; mt < 2; mt++) {
            int row = m0 + mt * 16 + a_row;
            int ch = c + a_chd;
            uint32_t o = (uint32_t)(row * 128 + ((ch ^ (row & 7)) * 16));
            ldsm4(ah[mt], aH + o);
            ldsm4(al[mt], aL + o);
        }
#pragma unroll
        for (int np = 0; np < 2; np++) {
            int row = n0 + np * 16 + b_row;
            int ch = c + b_chd;
            uint32_t o = (uint32_t)(row * 128 + ((ch ^ (row & 7)) * 16));
            ldsm4(bh[np], bH + o);
            ldsm4(bl[np], bL + o);
        }
#pragma unroll
        for (int mt = 0; mt < 2; mt++)
#pragma unroll
            for (int nt = 0; nt < 4; nt++) {
                const uint32_t* fh = &bh[nt >> 1][(nt & 1) * 2];
                const uint32_t* fl = &bl[nt >> 1][(nt & 1) * 2];
                mma16816(d[mt][nt], ah[mt], fh);   // hi*hi
                mma16816(d[mt][nt], ah[mt], fl);   // hi*lo
                mma16816(d[mt][nt], al[mt], fh);   // lo*hi
            }
    }
}

__global__ void __launch_bounds__(512, 1)
k_gemm_mma(const __nv_bfloat16* __restrict__ wlh, const __nv_bfloat16* __restrict__ wll,
           const __nv_bfloat16* __restrict__ wrh, const __nv_bfloat16* __restrict__ wrl,
           const float* __restrict__ bias, float* __restrict__ zout, int stats_layer) {
    extern __shared__ char smb[];
    uint32_t sb = smem_u32(smb);
    const int t = threadIdx.x, wid = t >> 5, lane = t & 31;
    const int m0 = (wid & 3) * 32;
    const int n0 = (wid >> 2) * 32;
    const int row0 = blockIdx.x * MT;
    const int g = lane >> 2, tid4 = lane & 3;
    const int do_stats = (stats_layer >= 0);

    const int a_row = lane & 15, a_chd = lane >> 4;
    const int b_row = (lane & 7) + ((lane >> 4) << 3), b_chd = (lane >> 3) & 1;

    float d[2][4][4];
#pragma unroll
    for (int mt = 0; mt < 2; mt++)
#pragma unroll
        for (int nt = 0; nt < 4; nt++)
#pragma unroll
            for (int j = 0; j < 4; j++) d[mt][nt][j] = 0.f;

    const __nv_bfloat16* Ah[4] = {g_aggh, g_aggh, g_zh, g_zh};
    const __nv_bfloat16* Al[4] = {g_aggl, g_aggl, g_zl, g_zl};
    const __nv_bfloat16* Bh[4] = {wlh, wlh, wrh, wrh};
    const __nv_bfloat16* Bl[4] = {wll, wll, wrl, wrl};

    stage_chunk(sb, 0, Ah[0], Al[0], Bh[0], Bl[0], 0, row0, t);
#pragma unroll
    for (int c = 0; c < 4; c++) {
        if (c + 1 < 4) {
            stage_chunk(sb, (c + 1) & 1, Ah[c + 1], Al[c + 1], Bh[c + 1], Bl[c + 1],
                        ((c + 1) & 1) * 64, row0, t);
            asm volatile("cp.async.wait_group 1;" ::: "memory");
        } else {
            asm volatile("cp.async.wait_group 0;" ::: "memory");
        }
        __syncthreads();
        compute_chunk(sb, c & 1, m0, n0, a_row, a_chd, b_row, b_chd, d);
        __syncthreads();
    }

    float* ssum = (float*)smb;
    float* ssq  = ssum + HH;
    if (do_stats && t < 2 * HH) ssum[t] = 0.f;
    __syncthreads();

    float s_acc[4][2], q_acc[4][2];
#pragma unroll
    for (int nt = 0; nt < 4; nt++) { s_acc[nt][0] = s_acc[nt][1] = 0.f; q_acc[nt][0] = q_acc[nt][1] = 0.f; }

#pragma unroll
    for (int mt = 0; mt < 2; mt++) {
        int r_up = row0 + m0 + mt * 16 + g;
        int r_dn = r_up + 8;
#pragma unroll
        for (int nt = 0; nt < 4; nt++) {
            int cc = n0 + nt * 8 + tid4 * 2;
            float b0 = bias[cc], b1 = bias[cc + 1];
            if (r_up < NN) {
                float v0 = d[mt][nt][0] + b0, v1 = d[mt][nt][1] + b1;
                *(float2*)&zout[(size_t)r_up * HH + cc] = make_float2(v0, v1);
                s_acc[nt][0] += v0; q_acc[nt][0] = fmaf(v0, v0, q_acc[nt][0]);
                s_acc[nt][1] += v1; q_acc[nt][1] = fmaf(v1, v1, q_acc[nt][1]);
            }
            if (r_dn < NN) {
                float v2 = d[mt][nt][2] + b0, v3 = d[mt][nt][3] + b1;
                *(float2*)&zout[(size_t)r_dn * HH + cc] = make_float2(v2, v3);
                s_acc[nt][0] += v2; q_acc[nt][0] = fmaf(v2, v2, q_acc[nt][0]);
                s_acc[nt][1] += v3; q_acc[nt][1] = fmaf(v3, v3, q_acc[nt][1]);
            }
        }
    }

    if (do_stats) {
#pragma unroll
        for (int nt = 0; nt < 4; nt++)
#pragma unroll
            for (int j = 0; j < 2; j++) {
                float sv = s_acc[nt][j], qv = q_acc[nt][j];
                sv += __shfl_down_sync(0xFFFFFFFFu, sv, 16);
                qv += __shfl_down_sync(0xFFFFFFFFu, qv, 16);
                sv += __shfl_down_sync(0xFFFFFFFFu, sv, 8);
                qv += __shfl_down_sync(0xFFFFFFFFu, qv, 8);
                sv += __shfl_down_sync(0xFFFFFFFFu, sv, 4);
                qv += __shfl_down_sync(0xFFFFFFFFu, qv, 4);
                if (g == 0) {
                    int cc = n0 + nt * 8 + tid4 * 2 + j;
                    atomicAdd(&ssum[cc], sv);
                    atomicAdd(&ssq[cc], qv);
                }
            }
        __syncthreads();
        if (t < HH) {
            atomicAdd(&g_bnsum[(size_t)stats_layer * HH + t], ssum[t]);
            atomicAdd(&g_bnsq[(size_t)stats_layer * HH + t], ssq[t]);
        }
    }
}

// ---------------- decoder ----------------
__global__ void k_dec(const float* __restrict__ z, const float* __restrict__ dW,
                      const float* __restrict__ db, float* __restrict__ out) {
    __shared__ float W[HH * OUTF];
    for (int i = threadIdx.x; i < HH * OUTF; i += blockDim.x) W[i] = dW[i];
    __syncthreads();
    int w = (blockIdx.x * blockDim.x + threadIdx.x) >> 5;
    int lane = threadIdx.x & 31;
    if (w >= NN) return;
    float4 zv = *(const float4*)&z[(size_t)w * HH + lane * 4];
    int h = lane * 4;
    float o0 = zv.x * W[h * 4 + 0] + zv.y * W[(h + 1) * 4 + 0] + zv.z * W[(h + 2) * 4 + 0] + zv.w * W[(h + 3) * 4 + 0];
    float o1 = zv.x * W[h * 4 + 1] + zv.y * W[(h + 1) * 4 + 1] + zv.z * W[(h + 2) * 4 + 1] + zv.w * W[(h + 3) * 4 + 1];
    float o2 = zv.x * W[h * 4 + 2] + zv.y * W[(h + 1) * 4 + 2] + zv.z * W[(h + 2) * 4 + 2] + zv.w * W[(h + 3) * 4 + 2];
    float o3 = zv.x * W[h * 4 + 3] + zv.y * W[(h + 1) * 4 + 3] + zv.z * W[(h + 2) * 4 + 3] + zv.w * W[(h + 3) * 4 + 3];
#pragma unroll
    for (int d = 16; d; d >>= 1) {
        o0 += __shfl_down_sync(0xFFFFFFFFu, o0, d);
        o1 += __shfl_down_sync(0xFFFFFFFFu, o1, d);
        o2 += __shfl_down_sync(0xFFFFFFFFu, o2, d);
        o3 += __shfl_down_sync(0xFFFFFFFFu, o3, d);
    }
    if (lane == 0) {
        float4 r;
        r.x = o0 + db[0]; r.y = o1 + db[1]; r.z = o2 + db[2]; r.w = o3 + db[3];
        *(float4*)&out[w * 4] = r;
    }
}

// ---------------- launch ----------------
extern "C" void kernel_launch(void* const* d_in, const int* in_sizes, int n_in,
                              void* d_out, int out_size) {
    const float* x      = (const float*)d_in[0];
    const float* enc_W  = (const float*)d_in[1];
    const float* enc_b  = (const float*)d_in[2];
    const float* Wl     = (const float*)d_in[3];
    const float* Wr     = (const float*)d_in[4];
    const float* b      = (const float*)d_in[5];
    const float* bng    = (const float*)d_in[6];
    const float* bnb    = (const float*)d_in[7];
    const float* dec_W  = (const float*)d_in[8];
    const float* dec_b  = (const float*)d_in[9];
    const int*   ei     = (const int*)d_in[10];
    float* out = (float*)d_out;

    float *zA, *zB;
    __nv_bfloat16 *Wth, *Wtl;
    void* p;
    cudaGetSymbolAddress(&p, g_zA);  zA  = (float*)p;
    cudaGetSymbolAddress(&p, g_zB);  zB  = (float*)p;
    cudaGetSymbolAddress(&p, g_Wth); Wth = (__nv_bfloat16*)p;
    cudaGetSymbolAddress(&p, g_Wtl); Wtl = (__nv_bfloat16*)p;
    void* pdeg;
    cudaGetSymbolAddress(&pdeg, g_deg);

    cudaFuncSetAttribute(k_gemm_mma, cudaFuncAttributeMaxDynamicSharedMemorySize, GEMM_SMEM);

    const int TB = 256;
    const int egrid = (EE + TB - 1) / TB;
    const int nblk1024 = (NN + 1023) / 1024;

    // CSR build + W conversion
    cudaMemsetAsync(pdeg, 0, NN * sizeof(int));
    k_degree<<<egrid, TB>>>(ei);
    k_scan1<<<nblk1024, 1024>>>();
    k_scan3<<<(NN + TB - 1) / TB, TB>>>(nblk1024);
    k_scatter<<<egrid, TB>>>(ei);
    k_wconv<<<(2 * NL * HH * HH + TB - 1) / TB, TB>>>(Wl, Wr);

    k_enc<<<(NN * HH + TB - 1) / TB, TB>>>(x, enc_W, enc_b, zA);

    float* zin = zA;
    float* zout = zB;
    for (int i = 0; i < NL; i++) {
        if (i > 0)
            k_bnfin<<<1, HH>>>(i - 1, bng + (size_t)(i - 1) * HH, bnb + (size_t)(i - 1) * HH);
        k_agg<<<(NN * 32 + TB - 1) / TB, TB>>>(zin, i > 0);
        k_gemm_mma<<<NTILES, 512, GEMM_SMEM>>>(
            Wth + (size_t)(2 * i + 0) * HH * HH, Wtl + (size_t)(2 * i + 0) * HH * HH,
            Wth + (size_t)(2 * i + 1) * HH * HH, Wtl + (size_t)(2 * i + 1) * HH * HH,
            b + (size_t)i * HH, zout, (i < NL - 1) ? i : -1);
        float* tmp = zin; zin = zout; zout = tmp;
    }

    k_dec<<<(NN * 32 + TB - 1) / TB, TB>>>(zin, dec_W, dec_b, out);
}